// round 10
// baseline (speedup 1.0000x reference)
#include <cuda_runtime.h>
#include <cuda_bf16.h>

// Problem constants (fixed by setup_inputs)
#define BATCH 32
#define TSEQ  1024
#define DIM   512
#define NMAX  500000
#define MAXK  64

#define FULLMASK 0xffffffffu
#define NEG_BIG (-3.0e38f)

#define SEGS2 16
#define RSEG  32
#define CAP   16384
#define MAXBLK 2048

// tensor-core scores tiling
#define TCN 256        // keys per block
#define KC  64         // k-chunk
#define KS  72         // key row stride in bf16
#define QS  520        // query row stride in bf16

#define SCALE_D 0.044194173824159216f  // 1/sqrt(512)

// ---------------- device scratch (no allocations allowed) ----------------
__device__ float          g_query[BATCH * DIM];
__device__ unsigned short g_sbf[(size_t)BATCH * NMAX];   // approx scores, bf16 bits (32 MB)
__device__ unsigned       g_bmax[BATCH * MAXBLK];        // per-(row, score-block) max (mapped u16)
__device__ unsigned       g_thr[BATCH];
__device__ int            g_cnt[BATCH];
__device__ float          g_cv[BATCH * CAP];
__device__ int            g_ci[BATCH * CAP];
__device__ float          g_topv[BATCH * MAXK];
__device__ int            g_topi[BATCH * MAXK];

// monotone map on bf16 bit pattern: a > b (as floats) <=> map16(a) > map16(b)
__device__ __forceinline__ unsigned map16(unsigned u) {
    unsigned s = u >> 15;
    return (u ^ (0x8000u | (0x7FFFu & (0u - s)))) & 0xFFFFu;
}

// ---------------- kernel 1: fused mean-pool + query GEMM ----------------
// grid = BATCH, 1024 threads. Phase A: two half-T partial sums; Phase B: query = mean @ W + b.
__global__ void __launch_bounds__(1024)
k_poolquery(const float* __restrict__ hidden,
            const float* __restrict__ W, const float* __restrict__ bias) {
    int b = blockIdx.x;
    int tid = threadIdx.x;
    int j = tid & (DIM - 1);
    int h = tid >> 9;               // 0 or 1
    __shared__ float spart[2][DIM];
    __shared__ float sp[DIM];

    const float* base = hidden + ((size_t)b * TSEQ + h * (TSEQ / 2)) * DIM;
    float a = 0.f;
#pragma unroll 4
    for (int t = 0; t < TSEQ / 2; ++t) a += base[t * DIM + j];
    spart[h][j] = a;
    __syncthreads();
    if (tid < DIM) sp[tid] = (spart[0][tid] + spart[1][tid]) * (1.0f / (float)TSEQ);
    __syncthreads();
    if (tid < DIM) {
        float q = bias[tid];
#pragma unroll 8
        for (int d = 0; d < DIM; ++d) q += sp[d] * W[d * DIM + tid];
        g_query[b * DIM + tid] = q;
    }
}

// ---------------- mma.sync m16n8k16 bf16 wrapper ----------------
__device__ __forceinline__ void mma_bf16(float c[4],
                                         unsigned a0, unsigned a1, unsigned a2, unsigned a3,
                                         unsigned b0, unsigned b1) {
    asm volatile(
        "mma.sync.aligned.m16n8k16.row.col.f32.bf16.bf16.f32 "
        "{%0,%1,%2,%3}, {%4,%5,%6,%7}, {%8,%9}, {%0,%1,%2,%3};"
        : "+f"(c[0]), "+f"(c[1]), "+f"(c[2]), "+f"(c[3])
        : "r"(a0), "r"(a1), "r"(a2), "r"(a3), "r"(b0), "r"(b1));
}

__device__ __forceinline__ unsigned pack_bf16x2(float lo, float hi) {
    __nv_bfloat162 p = __floats2bfloat162_rn(lo, hi);
    return *reinterpret_cast<unsigned*>(&p);
}

// ---------------- kernel 2: approx scores via tensor cores + per-tile row max ----------------
// Epilogue stages output in smem, then writes fully-coalesced 512B rows.
__global__ void __launch_bounds__(256, 2)
k_scores_tc(const float* __restrict__ keys, int N) {
    extern __shared__ __nv_bfloat16 sm[];
    __nv_bfloat16* qs = sm;              // [32][QS]
    __nv_bfloat16* ks = sm + BATCH * QS; // [TCN][KS]  (reused as output stage)
    __shared__ unsigned srmax[BATCH];

    int tid = threadIdx.x;
    int w = tid >> 5, lane = tid & 31;
    int g = lane >> 2, tig = lane & 3;
    int n0 = blockIdx.x * TCN;

    if (tid < BATCH) srmax[tid] = 0u;

    // load queries fp32 -> bf16 smem
#pragma unroll
    for (int it = 0; it < 16; ++it) {
        int f = tid + it * 256;
        int row = f >> 7;
        int kq = f & 127;
        float4 v = *reinterpret_cast<const float4*>(&g_query[row * DIM + kq * 4]);
        unsigned p0 = pack_bf16x2(v.x, v.y);
        unsigned p1 = pack_bf16x2(v.z, v.w);
        unsigned long long pk = ((unsigned long long)p1 << 32) | p0;
        *reinterpret_cast<unsigned long long*>(&qs[row * QS + kq * 4]) = pk;
    }

    float acc[2][4][4];
#pragma unroll
    for (int mt = 0; mt < 2; ++mt)
#pragma unroll
        for (int nt = 0; nt < 4; ++nt)
#pragma unroll
            for (int r = 0; r < 4; ++r) acc[mt][nt][r] = 0.f;

    for (int kt = 0; kt < DIM / KC; ++kt) {
        __syncthreads();
#pragma unroll
        for (int it = 0; it < 16; ++it) {
            int f = tid + it * 256;
            int key = f >> 4;
            int kq = f & 15;
            int gk = n0 + key;
            float4 v = make_float4(0.f, 0.f, 0.f, 0.f);
            if (gk < N)
                v = *reinterpret_cast<const float4*>(&keys[(size_t)gk * DIM + kt * KC + kq * 4]);
            unsigned p0 = pack_bf16x2(v.x, v.y);
            unsigned p1 = pack_bf16x2(v.z, v.w);
            unsigned long long pk = ((unsigned long long)p1 << 32) | p0;
            *reinterpret_cast<unsigned long long*>(&ks[key * KS + kq * 4]) = pk;
        }
        __syncthreads();

#pragma unroll
        for (int s = 0; s < KC / 16; ++s) {
            int k0 = s * 16;
            unsigned a[2][4];
#pragma unroll
            for (int mt = 0; mt < 2; ++mt) {
                const __nv_bfloat16* alo = &qs[(mt * 16 + g) * QS + kt * KC + k0 + tig * 2];
                const __nv_bfloat16* ahi = alo + 8 * QS;
                a[mt][0] = *reinterpret_cast<const unsigned*>(alo);
                a[mt][1] = *reinterpret_cast<const unsigned*>(ahi);
                a[mt][2] = *reinterpret_cast<const unsigned*>(alo + 8);
                a[mt][3] = *reinterpret_cast<const unsigned*>(ahi + 8);
            }
#pragma unroll
            for (int nt = 0; nt < 4; ++nt) {
                const __nv_bfloat16* bp = &ks[(w * 32 + nt * 8 + g) * KS + k0 + tig * 2];
                unsigned b0 = *reinterpret_cast<const unsigned*>(bp);
                unsigned b1 = *reinterpret_cast<const unsigned*>(bp + 8);
                mma_bf16(acc[0][nt], a[0][0], a[0][1], a[0][2], a[0][3], b0, b1);
                mma_bf16(acc[1][nt], a[1][0], a[1][1], a[1][2], a[1][3], b0, b1);
            }
        }
    }

    // pack + per-row max (guard cols >= N out of the max)
    unsigned plo[2][4], phi[2][4];
    unsigned mlo[2] = {0u, 0u}, mhi[2] = {0u, 0u};
#pragma unroll
    for (int mt = 0; mt < 2; ++mt) {
#pragma unroll
        for (int nt = 0; nt < 4; ++nt) {
            plo[mt][nt] = pack_bf16x2(acc[mt][nt][0] * SCALE_D, acc[mt][nt][1] * SCALE_D);
            phi[mt][nt] = pack_bf16x2(acc[mt][nt][2] * SCALE_D, acc[mt][nt][3] * SCALE_D);
            int col = n0 + w * 32 + nt * 8 + tig * 2;
            if (col < N) {
                unsigned u;
                u = map16(plo[mt][nt] & 0xFFFFu); if (u > mlo[mt]) mlo[mt] = u;
                u = map16(plo[mt][nt] >> 16);     if (u > mlo[mt]) mlo[mt] = u;
                u = map16(phi[mt][nt] & 0xFFFFu); if (u > mhi[mt]) mhi[mt] = u;
                u = map16(phi[mt][nt] >> 16);     if (u > mhi[mt]) mhi[mt] = u;
            }
        }
    }

    // stage in smem (reuse ks region), then coalesced global write
    __syncthreads();   // everyone done reading ks
    unsigned short* stage = reinterpret_cast<unsigned short*>(ks);  // [32][256]
#pragma unroll
    for (int mt = 0; mt < 2; ++mt) {
#pragma unroll
        for (int nt = 0; nt < 4; ++nt) {
            int col = w * 32 + nt * 8 + tig * 2;
            int row_lo = mt * 16 + g;
            *reinterpret_cast<unsigned*>(&stage[row_lo * 256 + col])       = plo[mt][nt];
            *reinterpret_cast<unsigned*>(&stage[(row_lo + 8) * 256 + col]) = phi[mt][nt];
        }
    }
    __syncthreads();

    bool fast = ((N & 7) == 0);
#pragma unroll
    for (int rr = 0; rr < 4; ++rr) {
        int r = w + rr * 8;                 // batch row 0..31
        int gcol = n0 + lane * 8;
        uint4 v = reinterpret_cast<const uint4*>(stage)[r * 32 + lane];
        if (fast && gcol + 7 < N) {
            *reinterpret_cast<uint4*>(&g_sbf[(size_t)r * N + gcol]) = v;
        } else {
            unsigned vv[4] = {v.x, v.y, v.z, v.w};
#pragma unroll
            for (int q = 0; q < 8; ++q) {
                int c = gcol + q;
                if (c < N)
                    g_sbf[(size_t)r * N + c] =
                        (unsigned short)((vv[q >> 1] >> ((q & 1) * 16)) & 0xFFFFu);
            }
        }
    }

#pragma unroll
    for (int mt = 0; mt < 2; ++mt) {
        atomicMax(&srmax[mt * 16 + g], mlo[mt]);
        atomicMax(&srmax[mt * 16 + 8 + g], mhi[mt]);
    }
    __syncthreads();
    if (tid < BATCH) g_bmax[tid * MAXBLK + blockIdx.x] = srmax[tid];
}

// ---------------- kernel 3: per-row max -> conservative threshold; zero counters ----------------
__global__ void __launch_bounds__(256)
k_rowmax(int nblk) {
    int row = blockIdx.x;
    int tid = threadIdx.x;
    __shared__ unsigned sm[256];
    unsigned m = 0u;
    for (int i = tid; i < nblk; i += 256) {
        unsigned v = g_bmax[row * MAXBLK + i];
        if (v > m) m = v;
    }
    sm[tid] = m;
    __syncthreads();
    for (int o = 128; o; o >>= 1) {
        if (tid < o) { if (sm[tid + o] > sm[tid]) sm[tid] = sm[tid + o]; }
        __syncthreads();
    }
    if (tid == 0) {
        unsigned maxbin = sm[0] >> 5;           // quarter-octave bins
        unsigned tb = (maxbin > 4u) ? (maxbin - 4u) : 0u;  // threshold = max/2
        g_thr[row] = tb << 5;
        g_cnt[row] = 0;
    }
}

// ---------------- kernel 4 (PROFILE SLOT 3): collect candidate indices >= threshold ----------------
__global__ void __launch_bounds__(256)
k_filter(int N) {
    int row = blockIdx.x / SEGS2;
    int seg = blockIdx.x % SEGS2;
    int tid = threadIdx.x;
    unsigned thr = g_thr[row];

    int chunk = (((N + SEGS2 - 1) / SEGS2) + 7) & ~7;
    int s0 = seg * chunk;
    int s1 = s0 + chunk; if (s1 > N) s1 = N;
    const unsigned short* S = g_sbf + (size_t)row * N;

    for (int i = s0 + tid * 8; i < s1; i += 256 * 8) {
        if (i + 7 < s1) {
            uint4 x = *reinterpret_cast<const uint4*>(S + i);
            unsigned v[4] = {x.x, x.y, x.z, x.w};
#pragma unroll
            for (int q = 0; q < 4; ++q) {
                if (map16(v[q] & 0xFFFFu) >= thr) {
                    int pos = atomicAdd(&g_cnt[row], 1);
                    if (pos < CAP) g_ci[row * CAP + pos] = i + q * 2;
                }
                if (map16(v[q] >> 16) >= thr) {
                    int pos = atomicAdd(&g_cnt[row], 1);
                    if (pos < CAP) g_ci[row * CAP + pos] = i + q * 2 + 1;
                }
            }
        } else {
            for (int q = i; q < s1; ++q) {
                if (map16(S[q]) >= thr) {
                    int pos = atomicAdd(&g_cnt[row], 1);
                    if (pos < CAP) g_ci[row * CAP + pos] = q;
                }
            }
        }
    }
}

// ---------------- kernel 5: exact fp32 rescore of candidates ----------------
__global__ void __launch_bounds__(256)
k_rescore(const float* __restrict__ keys) {
    int row = blockIdx.x / RSEG;
    int seg = blockIdx.x % RSEG;
    int w = threadIdx.x >> 5, lane = threadIdx.x & 31;
    int cnt = g_cnt[row]; if (cnt > CAP) cnt = CAP;
    const float* q = g_query + row * DIM;

    for (int c = seg * 8 + w; c < cnt; c += 8 * RSEG) {
        int idx = g_ci[row * CAP + c];
        const float* kp = keys + (size_t)idx * DIM;
        float s = 0.f;
#pragma unroll
        for (int j = 0; j < 4; ++j) {
            float4 kv = *reinterpret_cast<const float4*>(kp + lane * 16 + j * 4);
            float4 qv = *reinterpret_cast<const float4*>(q + lane * 16 + j * 4);
            s += kv.x * qv.x + kv.y * qv.y + kv.z * qv.z + kv.w * qv.w;
        }
#pragma unroll
        for (int o = 16; o; o >>= 1) s += __shfl_xor_sync(FULLMASK, s, o);
        if (lane == 0) g_cv[row * CAP + c] = s * SCALE_D;
    }
}

// ---------------- warp helpers for exact merge ----------------
__device__ __forceinline__ float warp_min32(float v) {
#pragma unroll
    for (int o = 16; o; o >>= 1) v = fminf(v, __shfl_xor_sync(FULLMASK, v, o));
    return v;
}

__device__ __forceinline__ void topk_insert4(float a0, float a1, float a2, float a3,
                                             int base, float& v0, float& v1,
                                             int& i0, int& i1, float& thr) {
    unsigned pm = (unsigned)(a0 > thr) | ((unsigned)(a1 > thr) << 1) |
                  ((unsigned)(a2 > thr) << 2) | ((unsigned)(a3 > thr) << 3);
    while (__any_sync(FULLMASK, pm != 0)) {
        int c = __ffs(pm) - 1;
        float cv = (c == 0) ? a0 : (c == 1) ? a1 : (c == 2) ? a2 : a3;
        int ci = base + c;
        unsigned ball = __ballot_sync(FULLMASK, pm != 0);
        int src = __ffs(ball) - 1;
        float cand = __shfl_sync(FULLMASK, cv, src);
        int candi = __shfl_sync(FULLMASK, ci, src);
        int lane = threadIdx.x & 31;
        if (lane == src) pm &= pm - 1;
        if (cand > thr) {
            float mn = fminf(v0, v1);
            float wmn = warp_min32(mn);
            unsigned who = __ballot_sync(FULLMASK, mn == wmn);
            int wl = __ffs(who) - 1;
            if (lane == wl) {
                if (v0 <= v1) { v0 = cand; i0 = candi; }
                else          { v1 = cand; i1 = candi; }
            }
            thr = warp_min32(fminf(v0, v1));
        }
        if (pm) {
            if ((pm & 1u) && a0 <= thr) pm &= ~1u;
            if ((pm & 2u) && a1 <= thr) pm &= ~2u;
            if ((pm & 4u) && a2 <= thr) pm &= ~4u;
            if ((pm & 8u) && a3 <= thr) pm &= ~8u;
        }
    }
}

// ---------------- kernel 6: exact sorted top-64 from candidates ----------------
__global__ void __launch_bounds__(1024)
k_topk_merge() {
    int row = blockIdx.x;
    int tid = threadIdx.x;
    int lane = tid & 31;
    int wid = tid >> 5;

    int C = g_cnt[row]; if (C > CAP) C = CAP;
    const float* CV = g_cv + (size_t)row * CAP;
    const int*   CI = g_ci + (size_t)row * CAP;

    float v0 = NEG_BIG, v1 = NEG_BIG;
    int i0 = 0, i1 = 0;
    float thr = NEG_BIG;

    int iters = (C + 4095) >> 12;
    for (int it = 0; it < iters; ++it) {
        int f = (it << 12) + (tid << 2);
        float a0 = (f + 0 < C) ? CV[f + 0] : NEG_BIG;
        float a1 = (f + 1 < C) ? CV[f + 1] : NEG_BIG;
        float a2 = (f + 2 < C) ? CV[f + 2] : NEG_BIG;
        float a3 = (f + 3 < C) ? CV[f + 3] : NEG_BIG;
        topk_insert4(a0, a1, a2, a3, f, v0, v1, i0, i1, thr);
    }
    i0 = (v0 > NEG_BIG) ? CI[i0] : 0x7fffffff;
    i1 = (v1 > NEG_BIG) ? CI[i1] : 0x7fffffff;

    __shared__ float sv[2048];
    __shared__ int   si[2048];
    __shared__ float wv[32];
    __shared__ int   wp[32];
    __shared__ int   wsrc[32];
    sv[wid * 64 + lane]      = v0;  si[wid * 64 + lane]      = i0;
    sv[wid * 64 + 32 + lane] = v1;  si[wid * 64 + 32 + lane] = i1;
    __syncthreads();

    for (int j = 0; j < MAXK; ++j) {
        float bv = sv[wid * 64 + lane];      int bi = si[wid * 64 + lane];      int bp = wid * 64 + lane;
        float ov = sv[wid * 64 + 32 + lane]; int oi = si[wid * 64 + 32 + lane]; int op = wid * 64 + 32 + lane;
        if (ov > bv || (ov == bv && oi < bi)) { bv = ov; bi = oi; bp = op; }
#pragma unroll
        for (int o = 16; o; o >>= 1) {
            float xv = __shfl_xor_sync(FULLMASK, bv, o);
            int   xi = __shfl_xor_sync(FULLMASK, bi, o);
            int   xp = __shfl_xor_sync(FULLMASK, bp, o);
            if (xv > bv || (xv == bv && xi < bi)) { bv = xv; bi = xi; bp = xp; }
        }
        if (lane == 0) { wv[wid] = bv; wp[wid] = bi; wsrc[wid] = bp; }
        __syncthreads();
        if (wid == 0) {
            float cv2 = wv[lane]; int ci2 = wp[lane]; int cp2 = wsrc[lane];
#pragma unroll
            for (int o = 16; o; o >>= 1) {
                float xv = __shfl_xor_sync(FULLMASK, cv2, o);
                int   xi = __shfl_xor_sync(FULLMASK, ci2, o);
                int   xp = __shfl_xor_sync(FULLMASK, cp2, o);
                if (xv > cv2 || (xv == cv2 && xi < ci2)) { cv2 = xv; ci2 = xi; cp2 = xp; }
            }
            if (lane == 0) {
                g_topv[row * MAXK + j] = cv2;
                g_topi[row * MAXK + j] = ci2;
                sv[cp2] = NEG_BIG;
                si[cp2] = 0x7fffffff;
            }
        }
        __syncthreads();
    }
}

// ---------------- kernel 7: softmax(top-kd) + gather + weighted sum ----------------
__global__ void k_aggregate(const float* __restrict__ P,
                            const int* __restrict__ kdyn,
                            float* __restrict__ out) {
    int row = blockIdx.x;
    int tid = threadIdx.x;
    __shared__ float ws[MAXK];
    __shared__ int   idx[MAXK];
    __shared__ float s_inv;

    int kd = *kdyn;
    kd = kd < 0 ? 0 : (kd > MAXK ? MAXK : kd);

    if (tid < MAXK) {
        float v = g_topv[row * MAXK + tid];
        idx[tid] = g_topi[row * MAXK + tid];
        float m = (kd > 0) ? g_topv[row * MAXK] : -1e9f;
        float mv = (tid < kd) ? v : -1e9f;
        ws[tid] = expf(mv - m);
    }
    __syncthreads();
    if (tid == 0) {
        float s = 0.f;
#pragma unroll
        for (int j = 0; j < MAXK; ++j) s += ws[j];
        s_inv = 1.0f / s;
    }
    __syncthreads();

    float a = 0.f;
#pragma unroll 4
    for (int j = 0; j < MAXK; ++j) {
        float w = ws[j];
        if (w != 0.f) a += w * P[(size_t)idx[j] * DIM + tid];
    }
    out[row * DIM + tid] = a * s_inv;
}

// ---------------- launcher ----------------
extern "C" void kernel_launch(void* const* d_in, const int* in_sizes, int n_in,
                              void* d_out, int out_size) {
    const float* hidden      = (const float*)d_in[0];
    const float* pool_params = (const float*)d_in[1];
    const float* pool_keys   = (const float*)d_in[2];
    const float* W           = (const float*)d_in[3];
    const float* bias        = (const float*)d_in[4];
    const int*   k_dynamic   = (const int*)d_in[5];
    float* out = (float*)d_out;

    int N = in_sizes[2] / DIM;

    static const size_t SMEMTC = (size_t)(BATCH * QS + TCN * KS) * sizeof(__nv_bfloat16);
    cudaFuncSetAttribute(k_scores_tc, cudaFuncAttributeMaxDynamicSharedMemorySize, (int)SMEMTC);

    int nblk = (N + TCN - 1) / TCN;
    if (nblk > MAXBLK) nblk = MAXBLK;

    k_poolquery<<<BATCH, 1024>>>(hidden, W, bias);          // launch 0
    k_scores_tc<<<nblk, 256, SMEMTC>>>(pool_keys, N);       // launch 1
    k_rowmax<<<BATCH, 256>>>(nblk);                         // launch 2
    k_filter<<<BATCH * SEGS2, 256>>>(N);                    // launch 3  <-- profile slot
    k_rescore<<<BATCH * RSEG, 256>>>(pool_keys);            // launch 4
    k_topk_merge<<<BATCH, 1024>>>();                        // launch 5
    k_aggregate<<<BATCH, DIM>>>(pool_params, k_dynamic, out); // launch 6
}

// round 11
// speedup vs baseline: 1.4338x; 1.4338x over previous
#include <cuda_runtime.h>
#include <cuda_bf16.h>

// Problem constants (fixed by setup_inputs)
#define BATCH 32
#define TSEQ  1024
#define DIM   512
#define NMAX  500000
#define MAXK  64

#define FULLMASK 0xffffffffu
#define NEG_BIG (-3.0e38f)

#define SEGS2 32
#define RSEG  64
#define CAP   16384
#define MAXBLK 2048

// tensor-core scores tiling
#define TCN 256        // keys per block
#define KC  64         // k-chunk
#define KS  72         // key row stride in bf16
#define QS  520        // query row stride in bf16

#define SCALE_D 0.044194173824159216f  // 1/sqrt(512)

// ---------------- device scratch (no allocations allowed) ----------------
__device__ float          g_part[BATCH * 8 * DIM];
__device__ float          g_query[BATCH * DIM];
__device__ unsigned short g_sbf[(size_t)BATCH * NMAX];   // approx scores, bf16 bits (32 MB)
__device__ unsigned       g_bmax[BATCH * MAXBLK];        // per-(row, score-block) max (mapped u16)
__device__ unsigned       g_thr[BATCH];
__device__ int            g_cnt[BATCH];
__device__ float          g_cv[BATCH * CAP];
__device__ int            g_ci[BATCH * CAP];
__device__ float          g_topv[BATCH * MAXK];
__device__ int            g_topi[BATCH * MAXK];

// monotone map on bf16 bit pattern: a > b (as floats) <=> map16(a) > map16(b)
__device__ __forceinline__ unsigned map16(unsigned u) {
    unsigned s = u >> 15;
    return (u ^ (0x8000u | (0x7FFFu & (0u - s)))) & 0xFFFFu;
}

// ---------------- kernel: partial mean over T (256 blocks — full-chip) ----------------
__global__ void k_pool_partial(const float* __restrict__ hidden) {
    int b = blockIdx.x >> 3;
    int chunk = blockIdx.x & 7;
    int tid = threadIdx.x;
    const float* base = hidden + ((size_t)b * TSEQ + chunk * 128) * DIM;
    float a0 = 0.f, a1 = 0.f;
#pragma unroll 4
    for (int t = 0; t < 128; ++t) {
        a0 += base[t * DIM + tid];
        a1 += base[t * DIM + tid + 256];
    }
    g_part[(b * 8 + chunk) * DIM + tid]       = a0;
    g_part[(b * 8 + chunk) * DIM + tid + 256] = a1;
}

// ---------------- kernel: query = mean @ W + b ----------------
__global__ void k_query(const float* __restrict__ W, const float* __restrict__ bias) {
    int b = blockIdx.x;
    int j = threadIdx.x;
    __shared__ float sp[DIM];
    float s = 0.f;
#pragma unroll
    for (int c = 0; c < 8; ++c) s += g_part[(b * 8 + c) * DIM + j];
    sp[j] = s * (1.0f / (float)TSEQ);
    __syncthreads();
    float q = bias[j];
#pragma unroll 8
    for (int d = 0; d < DIM; ++d) q += sp[d] * W[d * DIM + j];
    g_query[b * DIM + j] = q;
}

// ---------------- kernel: zero per-row counters (also pads launch index) ----------------
__global__ void k_zero32() {
    if (threadIdx.x < BATCH) g_cnt[threadIdx.x] = 0;
}

// ---------------- mma.sync m16n8k16 bf16 wrapper ----------------
__device__ __forceinline__ void mma_bf16(float c[4],
                                         unsigned a0, unsigned a1, unsigned a2, unsigned a3,
                                         unsigned b0, unsigned b1) {
    asm volatile(
        "mma.sync.aligned.m16n8k16.row.col.f32.bf16.bf16.f32 "
        "{%0,%1,%2,%3}, {%4,%5,%6,%7}, {%8,%9}, {%0,%1,%2,%3};"
        : "+f"(c[0]), "+f"(c[1]), "+f"(c[2]), "+f"(c[3])
        : "r"(a0), "r"(a1), "r"(a2), "r"(a3), "r"(b0), "r"(b1));
}

__device__ __forceinline__ unsigned pack_bf16x2(float lo, float hi) {
    __nv_bfloat162 p = __floats2bfloat162_rn(lo, hi);
    return *reinterpret_cast<unsigned*>(&p);
}

// ---------------- kernel (PROFILE SLOT): approx scores via tensor cores ----------------
// Staged smem epilogue -> fully coalesced 512B-per-row stores.
__global__ void __launch_bounds__(256, 2)
k_scores_tc(const float* __restrict__ keys, int N) {
    extern __shared__ __nv_bfloat16 sm[];
    __nv_bfloat16* qs = sm;              // [32][QS]
    __nv_bfloat16* ks = sm + BATCH * QS; // [TCN][KS]  (reused as output stage)
    __shared__ unsigned srmax[BATCH];

    int tid = threadIdx.x;
    int w = tid >> 5, lane = tid & 31;
    int g = lane >> 2, tig = lane & 3;
    int n0 = blockIdx.x * TCN;

    if (tid < BATCH) srmax[tid] = 0u;

    // load queries fp32 -> bf16 smem
#pragma unroll
    for (int it = 0; it < 16; ++it) {
        int f = tid + it * 256;
        int row = f >> 7;
        int kq = f & 127;
        float4 v = *reinterpret_cast<const float4*>(&g_query[row * DIM + kq * 4]);
        unsigned p0 = pack_bf16x2(v.x, v.y);
        unsigned p1 = pack_bf16x2(v.z, v.w);
        unsigned long long pk = ((unsigned long long)p1 << 32) | p0;
        *reinterpret_cast<unsigned long long*>(&qs[row * QS + kq * 4]) = pk;
    }

    float acc[2][4][4];
#pragma unroll
    for (int mt = 0; mt < 2; ++mt)
#pragma unroll
        for (int nt = 0; nt < 4; ++nt)
#pragma unroll
            for (int r = 0; r < 4; ++r) acc[mt][nt][r] = 0.f;

    for (int kt = 0; kt < DIM / KC; ++kt) {
        __syncthreads();
#pragma unroll
        for (int it = 0; it < 16; ++it) {
            int f = tid + it * 256;
            int key = f >> 4;
            int kq = f & 15;
            int gk = n0 + key;
            float4 v = make_float4(0.f, 0.f, 0.f, 0.f);
            if (gk < N)
                v = *reinterpret_cast<const float4*>(&keys[(size_t)gk * DIM + kt * KC + kq * 4]);
            unsigned p0 = pack_bf16x2(v.x, v.y);
            unsigned p1 = pack_bf16x2(v.z, v.w);
            unsigned long long pk = ((unsigned long long)p1 << 32) | p0;
            *reinterpret_cast<unsigned long long*>(&ks[key * KS + kq * 4]) = pk;
        }
        __syncthreads();

#pragma unroll
        for (int s = 0; s < KC / 16; ++s) {
            int k0 = s * 16;
            unsigned a[2][4];
#pragma unroll
            for (int mt = 0; mt < 2; ++mt) {
                const __nv_bfloat16* alo = &qs[(mt * 16 + g) * QS + kt * KC + k0 + tig * 2];
                const __nv_bfloat16* ahi = alo + 8 * QS;
                a[mt][0] = *reinterpret_cast<const unsigned*>(alo);
                a[mt][1] = *reinterpret_cast<const unsigned*>(ahi);
                a[mt][2] = *reinterpret_cast<const unsigned*>(alo + 8);
                a[mt][3] = *reinterpret_cast<const unsigned*>(ahi + 8);
            }
#pragma unroll
            for (int nt = 0; nt < 4; ++nt) {
                const __nv_bfloat16* bp = &ks[(w * 32 + nt * 8 + g) * KS + k0 + tig * 2];
                unsigned b0 = *reinterpret_cast<const unsigned*>(bp);
                unsigned b1 = *reinterpret_cast<const unsigned*>(bp + 8);
                mma_bf16(acc[0][nt], a[0][0], a[0][1], a[0][2], a[0][3], b0, b1);
                mma_bf16(acc[1][nt], a[1][0], a[1][1], a[1][2], a[1][3], b0, b1);
            }
        }
    }

    // pack + per-row max (guard cols >= N out of the max)
    unsigned plo[2][4], phi[2][4];
    unsigned mlo[2] = {0u, 0u}, mhi[2] = {0u, 0u};
#pragma unroll
    for (int mt = 0; mt < 2; ++mt) {
#pragma unroll
        for (int nt = 0; nt < 4; ++nt) {
            plo[mt][nt] = pack_bf16x2(acc[mt][nt][0] * SCALE_D, acc[mt][nt][1] * SCALE_D);
            phi[mt][nt] = pack_bf16x2(acc[mt][nt][2] * SCALE_D, acc[mt][nt][3] * SCALE_D);
            int col = n0 + w * 32 + nt * 8 + tig * 2;
            if (col < N) {
                unsigned u;
                u = map16(plo[mt][nt] & 0xFFFFu); if (u > mlo[mt]) mlo[mt] = u;
                u = map16(plo[mt][nt] >> 16);     if (u > mlo[mt]) mlo[mt] = u;
                u = map16(phi[mt][nt] & 0xFFFFu); if (u > mhi[mt]) mhi[mt] = u;
                u = map16(phi[mt][nt] >> 16);     if (u > mhi[mt]) mhi[mt] = u;
            }
        }
    }

    // stage in smem (reuse ks region), then coalesced global write
    __syncthreads();   // everyone done reading ks
    unsigned short* stage = reinterpret_cast<unsigned short*>(ks);  // [32][256]
#pragma unroll
    for (int mt = 0; mt < 2; ++mt) {
#pragma unroll
        for (int nt = 0; nt < 4; ++nt) {
            int col = w * 32 + nt * 8 + tig * 2;
            int row_lo = mt * 16 + g;
            *reinterpret_cast<unsigned*>(&stage[row_lo * 256 + col])       = plo[mt][nt];
            *reinterpret_cast<unsigned*>(&stage[(row_lo + 8) * 256 + col]) = phi[mt][nt];
        }
    }
    __syncthreads();

    bool fast = ((N & 7) == 0);
#pragma unroll
    for (int rr = 0; rr < 4; ++rr) {
        int r = w + rr * 8;                 // batch row 0..31
        int gcol = n0 + lane * 8;
        uint4 v = reinterpret_cast<const uint4*>(stage)[r * 32 + lane];
        if (fast && gcol + 7 < N) {
            *reinterpret_cast<uint4*>(&g_sbf[(size_t)r * N + gcol]) = v;
        } else {
            unsigned vv[4] = {v.x, v.y, v.z, v.w};
#pragma unroll
            for (int q = 0; q < 8; ++q) {
                int c = gcol + q;
                if (c < N)
                    g_sbf[(size_t)r * N + c] =
                        (unsigned short)((vv[q >> 1] >> ((q & 1) * 16)) & 0xFFFFu);
            }
        }
    }

#pragma unroll
    for (int mt = 0; mt < 2; ++mt) {
        atomicMax(&srmax[mt * 16 + g], mlo[mt]);
        atomicMax(&srmax[mt * 16 + 8 + g], mhi[mt]);
    }
    __syncthreads();
    if (tid < BATCH) g_bmax[tid * MAXBLK + blockIdx.x] = srmax[tid];
}

// ---------------- kernel: per-row max -> conservative threshold (max/2) ----------------
__global__ void __launch_bounds__(256)
k_rowmax(int nblk) {
    int row = blockIdx.x;
    int tid = threadIdx.x;
    __shared__ unsigned sm[256];
    unsigned m = 0u;
    for (int i = tid; i < nblk; i += 256) {
        unsigned v = g_bmax[row * MAXBLK + i];
        if (v > m) m = v;
    }
    sm[tid] = m;
    __syncthreads();
    for (int o = 128; o; o >>= 1) {
        if (tid < o) { if (sm[tid + o] > sm[tid]) sm[tid] = sm[tid + o]; }
        __syncthreads();
    }
    if (tid == 0) {
        unsigned maxbin = sm[0] >> 5;           // quarter-octave bins
        unsigned tb = (maxbin > 4u) ? (maxbin - 4u) : 0u;  // threshold = max/2
        g_thr[row] = tb << 5;
    }
}

// ---------------- kernel: collect candidate indices >= threshold (MLP-batched) ----------------
__global__ void __launch_bounds__(256)
k_filter(int N) {
    int row = blockIdx.x / SEGS2;
    int seg = blockIdx.x % SEGS2;
    int tid = threadIdx.x;
    unsigned thr = g_thr[row];

    int chunk = (((N + SEGS2 - 1) / SEGS2) + 7) & ~7;   // multiple of 8
    int s0 = seg * chunk;
    if (s0 >= N) return;
    int s1 = s0 + chunk; if (s1 > N) s1 = N;
    const unsigned short* S = g_sbf + (size_t)row * N;
    const uint4* S4 = reinterpret_cast<const uint4*>(S + s0);   // s0 multiple of 8
    int n4 = (s1 - s0) >> 3;   // full uint4 (8-elem) packets

    int b4 = 0;
    // batched main loop: 4 independent uint4 loads per thread per iteration
    for (; b4 + 1024 <= n4; b4 += 1024) {
        uint4 x[4];
#pragma unroll
        for (int j = 0; j < 4; ++j) x[j] = S4[b4 + tid + j * 256];
#pragma unroll
        for (int j = 0; j < 4; ++j) {
            int e0 = s0 + ((b4 + tid + j * 256) << 3);
            unsigned vv[4] = {x[j].x, x[j].y, x[j].z, x[j].w};
#pragma unroll
            for (int q = 0; q < 4; ++q) {
                if (map16(vv[q] & 0xFFFFu) >= thr) {
                    int pos = atomicAdd(&g_cnt[row], 1);
                    if (pos < CAP) g_ci[row * CAP + pos] = e0 + q * 2;
                }
                if (map16(vv[q] >> 16) >= thr) {
                    int pos = atomicAdd(&g_cnt[row], 1);
                    if (pos < CAP) g_ci[row * CAP + pos] = e0 + q * 2 + 1;
                }
            }
        }
    }
    // remainder uint4s
    for (int i4 = b4 + tid; i4 < n4; i4 += 256) {
        uint4 x = S4[i4];
        int e0 = s0 + (i4 << 3);
        unsigned vv[4] = {x.x, x.y, x.z, x.w};
#pragma unroll
        for (int q = 0; q < 4; ++q) {
            if (map16(vv[q] & 0xFFFFu) >= thr) {
                int pos = atomicAdd(&g_cnt[row], 1);
                if (pos < CAP) g_ci[row * CAP + pos] = e0 + q * 2;
            }
            if (map16(vv[q] >> 16) >= thr) {
                int pos = atomicAdd(&g_cnt[row], 1);
                if (pos < CAP) g_ci[row * CAP + pos] = e0 + q * 2 + 1;
            }
        }
    }
    // scalar tail (s1 not multiple of 8, last segment only)
    for (int q = s0 + (n4 << 3) + tid; q < s1; q += 256) {
        if (map16(S[q]) >= thr) {
            int pos = atomicAdd(&g_cnt[row], 1);
            if (pos < CAP) g_ci[row * CAP + pos] = q;
        }
    }
}

// ---------------- kernel: exact fp32 rescore of candidates ----------------
__global__ void __launch_bounds__(256)
k_rescore(const float* __restrict__ keys) {
    int row = blockIdx.x / RSEG;
    int seg = blockIdx.x % RSEG;
    int w = threadIdx.x >> 5, lane = threadIdx.x & 31;
    int cnt = g_cnt[row]; if (cnt > CAP) cnt = CAP;
    const float* q = g_query + row * DIM;

    for (int c = seg * 8 + w; c < cnt; c += 8 * RSEG) {
        int idx = g_ci[row * CAP + c];
        const float* kp = keys + (size_t)idx * DIM;
        float s = 0.f;
#pragma unroll
        for (int j = 0; j < 4; ++j) {
            float4 kv = *reinterpret_cast<const float4*>(kp + lane * 16 + j * 4);
            float4 qv = *reinterpret_cast<const float4*>(q + lane * 16 + j * 4);
            s += kv.x * qv.x + kv.y * qv.y + kv.z * qv.z + kv.w * qv.w;
        }
#pragma unroll
        for (int o = 16; o; o >>= 1) s += __shfl_xor_sync(FULLMASK, s, o);
        if (lane == 0) g_cv[row * CAP + c] = s * SCALE_D;
    }
}

// ---------------- warp helpers for exact merge ----------------
__device__ __forceinline__ float warp_min32(float v) {
#pragma unroll
    for (int o = 16; o; o >>= 1) v = fminf(v, __shfl_xor_sync(FULLMASK, v, o));
    return v;
}

__device__ __forceinline__ void topk_insert4(float a0, float a1, float a2, float a3,
                                             int base, float& v0, float& v1,
                                             int& i0, int& i1, float& thr) {
    unsigned pm = (unsigned)(a0 > thr) | ((unsigned)(a1 > thr) << 1) |
                  ((unsigned)(a2 > thr) << 2) | ((unsigned)(a3 > thr) << 3);
    while (__any_sync(FULLMASK, pm != 0)) {
        int c = __ffs(pm) - 1;
        float cv = (c == 0) ? a0 : (c == 1) ? a1 : (c == 2) ? a2 : a3;
        int ci = base + c;
        unsigned ball = __ballot_sync(FULLMASK, pm != 0);
        int src = __ffs(ball) - 1;
        float cand = __shfl_sync(FULLMASK, cv, src);
        int candi = __shfl_sync(FULLMASK, ci, src);
        int lane = threadIdx.x & 31;
        if (lane == src) pm &= pm - 1;
        if (cand > thr) {
            float mn = fminf(v0, v1);
            float wmn = warp_min32(mn);
            unsigned who = __ballot_sync(FULLMASK, mn == wmn);
            int wl = __ffs(who) - 1;
            if (lane == wl) {
                if (v0 <= v1) { v0 = cand; i0 = candi; }
                else          { v1 = cand; i1 = candi; }
            }
            thr = warp_min32(fminf(v0, v1));
        }
        if (pm) {
            if ((pm & 1u) && a0 <= thr) pm &= ~1u;
            if ((pm & 2u) && a1 <= thr) pm &= ~2u;
            if ((pm & 4u) && a2 <= thr) pm &= ~4u;
            if ((pm & 8u) && a3 <= thr) pm &= ~8u;
        }
    }
}

// ---------------- kernel: exact sorted top-64 from candidates ----------------
__global__ void __launch_bounds__(1024)
k_topk_merge() {
    int row = blockIdx.x;
    int tid = threadIdx.x;
    int lane = tid & 31;
    int wid = tid >> 5;

    int C = g_cnt[row]; if (C > CAP) C = CAP;
    const float* CV = g_cv + (size_t)row * CAP;
    const int*   CI = g_ci + (size_t)row * CAP;

    float v0 = NEG_BIG, v1 = NEG_BIG;
    int i0 = 0, i1 = 0;
    float thr = NEG_BIG;

    int iters = (C + 4095) >> 12;
    for (int it = 0; it < iters; ++it) {
        int f = (it << 12) + (tid << 2);
        float a0 = (f + 0 < C) ? CV[f + 0] : NEG_BIG;
        float a1 = (f + 1 < C) ? CV[f + 1] : NEG_BIG;
        float a2 = (f + 2 < C) ? CV[f + 2] : NEG_BIG;
        float a3 = (f + 3 < C) ? CV[f + 3] : NEG_BIG;
        topk_insert4(a0, a1, a2, a3, f, v0, v1, i0, i1, thr);
    }
    i0 = (v0 > NEG_BIG) ? CI[i0] : 0x7fffffff;
    i1 = (v1 > NEG_BIG) ? CI[i1] : 0x7fffffff;

    __shared__ float sv[2048];
    __shared__ int   si[2048];
    __shared__ float wv[32];
    __shared__ int   wp[32];
    __shared__ int   wsrc[32];
    sv[wid * 64 + lane]      = v0;  si[wid * 64 + lane]      = i0;
    sv[wid * 64 + 32 + lane] = v1;  si[wid * 64 + 32 + lane] = i1;
    __syncthreads();

    for (int j = 0; j < MAXK; ++j) {
        float bv = sv[wid * 64 + lane];      int bi = si[wid * 64 + lane];      int bp = wid * 64 + lane;
        float ov = sv[wid * 64 + 32 + lane]; int oi = si[wid * 64 + 32 + lane]; int op = wid * 64 + 32 + lane;
        if (ov > bv || (ov == bv && oi < bi)) { bv = ov; bi = oi; bp = op; }
#pragma unroll
        for (int o = 16; o; o >>= 1) {
            float xv = __shfl_xor_sync(FULLMASK, bv, o);
            int   xi = __shfl_xor_sync(FULLMASK, bi, o);
            int   xp = __shfl_xor_sync(FULLMASK, bp, o);
            if (xv > bv || (xv == bv && xi < bi)) { bv = xv; bi = xi; bp = xp; }
        }
        if (lane == 0) { wv[wid] = bv; wp[wid] = bi; wsrc[wid] = bp; }
        __syncthreads();
        if (wid == 0) {
            float cv2 = wv[lane]; int ci2 = wp[lane]; int cp2 = wsrc[lane];
#pragma unroll
            for (int o = 16; o; o >>= 1) {
                float xv = __shfl_xor_sync(FULLMASK, cv2, o);
                int   xi = __shfl_xor_sync(FULLMASK, ci2, o);
                int   xp = __shfl_xor_sync(FULLMASK, cp2, o);
                if (xv > cv2 || (xv == cv2 && xi < ci2)) { cv2 = xv; ci2 = xi; cp2 = xp; }
            }
            if (lane == 0) {
                g_topv[row * MAXK + j] = cv2;
                g_topi[row * MAXK + j] = ci2;
                sv[cp2] = NEG_BIG;
                si[cp2] = 0x7fffffff;
            }
        }
        __syncthreads();
    }
}

// ---------------- kernel: softmax(top-kd) + gather + weighted sum ----------------
__global__ void k_aggregate(const float* __restrict__ P,
                            const int* __restrict__ kdyn,
                            float* __restrict__ out) {
    int row = blockIdx.x;
    int tid = threadIdx.x;
    __shared__ float ws[MAXK];
    __shared__ int   idx[MAXK];
    __shared__ float s_inv;

    int kd = *kdyn;
    kd = kd < 0 ? 0 : (kd > MAXK ? MAXK : kd);

    if (tid < MAXK) {
        float v = g_topv[row * MAXK + tid];
        idx[tid] = g_topi[row * MAXK + tid];
        float m = (kd > 0) ? g_topv[row * MAXK] : -1e9f;
        float mv = (tid < kd) ? v : -1e9f;
        ws[tid] = expf(mv - m);
    }
    __syncthreads();
    if (tid == 0) {
        float s = 0.f;
#pragma unroll
        for (int j = 0; j < MAXK; ++j) s += ws[j];
        s_inv = 1.0f / s;
    }
    __syncthreads();

    float a = 0.f;
#pragma unroll 4
    for (int j = 0; j < MAXK; ++j) {
        float w = ws[j];
        if (w != 0.f) a += w * P[(size_t)idx[j] * DIM + tid];
    }
    out[row * DIM + tid] = a * s_inv;
}

// ---------------- launcher ----------------
extern "C" void kernel_launch(void* const* d_in, const int* in_sizes, int n_in,
                              void* d_out, int out_size) {
    const float* hidden      = (const float*)d_in[0];
    const float* pool_params = (const float*)d_in[1];
    const float* pool_keys   = (const float*)d_in[2];
    const float* W           = (const float*)d_in[3];
    const float* bias        = (const float*)d_in[4];
    const int*   k_dynamic   = (const int*)d_in[5];
    float* out = (float*)d_out;

    int N = in_sizes[2] / DIM;

    static const size_t SMEMTC = (size_t)(BATCH * QS + TCN * KS) * sizeof(__nv_bfloat16);
    cudaFuncSetAttribute(k_scores_tc, cudaFuncAttributeMaxDynamicSharedMemorySize, (int)SMEMTC);

    int nblk = (N + TCN - 1) / TCN;
    if (nblk > MAXBLK) nblk = MAXBLK;

    k_pool_partial<<<BATCH * 8, 256>>>(hidden);               // 0
    k_query<<<BATCH, DIM>>>(W, bias);                         // 1
    k_zero32<<<1, 32>>>();                                    // 2
    k_scores_tc<<<nblk, 256, SMEMTC>>>(pool_keys, N);         // 3  <-- profile slot
    k_rowmax<<<BATCH, 256>>>(nblk);                           // 4
    k_filter<<<BATCH * SEGS2, 256>>>(N);                      // 5
    k_rescore<<<BATCH * RSEG, 256>>>(pool_keys);              // 6
    k_topk_merge<<<BATCH, 1024>>>();                          // 7
    k_aggregate<<<BATCH, DIM>>>(pool_params, k_dynamic, out); // 8
}

// round 12
// speedup vs baseline: 1.7452x; 1.2172x over previous
#include <cuda_runtime.h>
#include <cuda_bf16.h>

// Problem constants (fixed by setup_inputs)
#define BATCH 32
#define TSEQ  1024
#define DIM   512
#define NMAX  500000
#define MAXK  64

#define FULLMASK 0xffffffffu
#define NEG_BIG (-3.0e38f)

#define SEGS2 32
#define RSEG  64
#define CAP   16384
#define MAXBLK 2048
#define FBUF  2048

// tensor-core scores tiling
#define TCN 256        // keys per block
#define KC  64         // k-chunk
#define KS  72         // key row stride in bf16
#define QS  520        // query row stride in bf16

#define SCALE_D 0.044194173824159216f  // 1/sqrt(512)

// ---------------- device scratch (no allocations allowed) ----------------
__device__ float          g_part[BATCH * 8 * DIM];
__device__ float          g_query[BATCH * DIM];
__device__ unsigned short g_sbf[(size_t)BATCH * NMAX];   // approx scores, bf16 bits (32 MB)
__device__ unsigned       g_bmax[BATCH * MAXBLK];        // per-(row, score-block) max (mapped u16)
__device__ unsigned       g_thr[BATCH];
__device__ int            g_cnt[BATCH];
__device__ float          g_cv[BATCH * CAP];
__device__ int            g_ci[BATCH * CAP];
__device__ float          g_topv[BATCH * MAXK];
__device__ int            g_topi[BATCH * MAXK];

// monotone map on bf16 bit pattern: a > b (as floats) <=> map16(a) > map16(b)
__device__ __forceinline__ unsigned map16(unsigned u) {
    unsigned s = u >> 15;
    return (u ^ (0x8000u | (0x7FFFu & (0u - s)))) & 0xFFFFu;
}

// ---------------- kernel: partial mean over T (256 blocks — full-chip) ----------------
__global__ void k_pool_partial(const float* __restrict__ hidden) {
    int b = blockIdx.x >> 3;
    int chunk = blockIdx.x & 7;
    int tid = threadIdx.x;
    const float* base = hidden + ((size_t)b * TSEQ + chunk * 128) * DIM;
    float a0 = 0.f, a1 = 0.f;
#pragma unroll 4
    for (int t = 0; t < 128; ++t) {
        a0 += base[t * DIM + tid];
        a1 += base[t * DIM + tid + 256];
    }
    g_part[(b * 8 + chunk) * DIM + tid]       = a0;
    g_part[(b * 8 + chunk) * DIM + tid + 256] = a1;
}

// ---------------- kernel: query = mean @ W + b ----------------
__global__ void k_query(const float* __restrict__ W, const float* __restrict__ bias) {
    int b = blockIdx.x;
    int j = threadIdx.x;
    __shared__ float sp[DIM];
    float s = 0.f;
#pragma unroll
    for (int c = 0; c < 8; ++c) s += g_part[(b * 8 + c) * DIM + j];
    sp[j] = s * (1.0f / (float)TSEQ);
    __syncthreads();
    float q = bias[j];
#pragma unroll 8
    for (int d = 0; d < DIM; ++d) q += sp[d] * W[d * DIM + j];
    g_query[b * DIM + j] = q;
}

// ---------------- kernel: zero per-row counters ----------------
__global__ void k_zero32() {
    if (threadIdx.x < BATCH) g_cnt[threadIdx.x] = 0;
}

// ---------------- mma.sync m16n8k16 bf16 wrapper ----------------
__device__ __forceinline__ void mma_bf16(float c[4],
                                         unsigned a0, unsigned a1, unsigned a2, unsigned a3,
                                         unsigned b0, unsigned b1) {
    asm volatile(
        "mma.sync.aligned.m16n8k16.row.col.f32.bf16.bf16.f32 "
        "{%0,%1,%2,%3}, {%4,%5,%6,%7}, {%8,%9}, {%0,%1,%2,%3};"
        : "+f"(c[0]), "+f"(c[1]), "+f"(c[2]), "+f"(c[3])
        : "r"(a0), "r"(a1), "r"(a2), "r"(a3), "r"(b0), "r"(b1));
}

__device__ __forceinline__ unsigned pack_bf16x2(float lo, float hi) {
    __nv_bfloat162 p = __floats2bfloat162_rn(lo, hi);
    return *reinterpret_cast<unsigned*>(&p);
}

// ---------------- kernel: approx scores via tensor cores (r7-proven epilogue) ----------------
__global__ void __launch_bounds__(256, 2)
k_scores_tc(const float* __restrict__ keys, int N) {
    extern __shared__ __nv_bfloat16 sm[];
    __nv_bfloat16* qs = sm;              // [32][QS]
    __nv_bfloat16* ks = sm + BATCH * QS; // [TCN][KS]
    __shared__ unsigned srmax[BATCH];

    int tid = threadIdx.x;
    int w = tid >> 5, lane = tid & 31;
    int g = lane >> 2, tig = lane & 3;
    int n0 = blockIdx.x * TCN;

    if (tid < BATCH) srmax[tid] = 0u;

    // load queries fp32 -> bf16 smem
#pragma unroll
    for (int it = 0; it < 16; ++it) {
        int f = tid + it * 256;
        int row = f >> 7;
        int kq = f & 127;
        float4 v = *reinterpret_cast<const float4*>(&g_query[row * DIM + kq * 4]);
        unsigned p0 = pack_bf16x2(v.x, v.y);
        unsigned p1 = pack_bf16x2(v.z, v.w);
        unsigned long long pk = ((unsigned long long)p1 << 32) | p0;
        *reinterpret_cast<unsigned long long*>(&qs[row * QS + kq * 4]) = pk;
    }

    float acc[2][4][4];
#pragma unroll
    for (int mt = 0; mt < 2; ++mt)
#pragma unroll
        for (int nt = 0; nt < 4; ++nt)
#pragma unroll
            for (int r = 0; r < 4; ++r) acc[mt][nt][r] = 0.f;

    for (int kt = 0; kt < DIM / KC; ++kt) {
        __syncthreads();
#pragma unroll
        for (int it = 0; it < 16; ++it) {
            int f = tid + it * 256;
            int key = f >> 4;
            int kq = f & 15;
            int gk = n0 + key;
            float4 v = make_float4(0.f, 0.f, 0.f, 0.f);
            if (gk < N)
                v = *reinterpret_cast<const float4*>(&keys[(size_t)gk * DIM + kt * KC + kq * 4]);
            unsigned p0 = pack_bf16x2(v.x, v.y);
            unsigned p1 = pack_bf16x2(v.z, v.w);
            unsigned long long pk = ((unsigned long long)p1 << 32) | p0;
            *reinterpret_cast<unsigned long long*>(&ks[key * KS + kq * 4]) = pk;
        }
        __syncthreads();

#pragma unroll
        for (int s = 0; s < KC / 16; ++s) {
            int k0 = s * 16;
            unsigned a[2][4];
#pragma unroll
            for (int mt = 0; mt < 2; ++mt) {
                const __nv_bfloat16* alo = &qs[(mt * 16 + g) * QS + kt * KC + k0 + tig * 2];
                const __nv_bfloat16* ahi = alo + 8 * QS;
                a[mt][0] = *reinterpret_cast<const unsigned*>(alo);
                a[mt][1] = *reinterpret_cast<const unsigned*>(ahi);
                a[mt][2] = *reinterpret_cast<const unsigned*>(alo + 8);
                a[mt][3] = *reinterpret_cast<const unsigned*>(ahi + 8);
            }
#pragma unroll
            for (int nt = 0; nt < 4; ++nt) {
                const __nv_bfloat16* bp = &ks[(w * 32 + nt * 8 + g) * KS + k0 + tig * 2];
                unsigned b0 = *reinterpret_cast<const unsigned*>(bp);
                unsigned b1 = *reinterpret_cast<const unsigned*>(bp + 8);
                mma_bf16(acc[0][nt], a[0][0], a[0][1], a[0][2], a[0][3], b0, b1);
                mma_bf16(acc[1][nt], a[1][0], a[1][1], a[1][2], a[1][3], b0, b1);
            }
        }
    }

    // epilogue: scattered bf16 stores + per-row tile max
    unsigned mlo[2] = {0u, 0u}, mhi[2] = {0u, 0u};
#pragma unroll
    for (int mt = 0; mt < 2; ++mt) {
#pragma unroll
        for (int nt = 0; nt < 4; ++nt) {
            int row_lo = mt * 16 + g;
            int row_hi = row_lo + 8;
            int col = n0 + w * 32 + nt * 8 + tig * 2;
            if (col < N) {
                unsigned plo = pack_bf16x2(acc[mt][nt][0] * SCALE_D, acc[mt][nt][1] * SCALE_D);
                unsigned phi = pack_bf16x2(acc[mt][nt][2] * SCALE_D, acc[mt][nt][3] * SCALE_D);
                *reinterpret_cast<unsigned*>(&g_sbf[(size_t)row_lo * N + col]) = plo;
                *reinterpret_cast<unsigned*>(&g_sbf[(size_t)row_hi * N + col]) = phi;
                unsigned u;
                u = map16(plo & 0xFFFFu); if (u > mlo[mt]) mlo[mt] = u;
                u = map16(plo >> 16);     if (u > mlo[mt]) mlo[mt] = u;
                u = map16(phi & 0xFFFFu); if (u > mhi[mt]) mhi[mt] = u;
                u = map16(phi >> 16);     if (u > mhi[mt]) mhi[mt] = u;
            }
        }
    }
    __syncthreads();
#pragma unroll
    for (int mt = 0; mt < 2; ++mt) {
        atomicMax(&srmax[mt * 16 + g], mlo[mt]);
        atomicMax(&srmax[mt * 16 + 8 + g], mhi[mt]);
    }
    __syncthreads();
    if (tid < BATCH) g_bmax[tid * MAXBLK + blockIdx.x] = srmax[tid];
}

// ---------------- kernel: per-row max -> conservative threshold (max/2) ----------------
__global__ void __launch_bounds__(256)
k_rowmax(int nblk) {
    int row = blockIdx.x;
    int tid = threadIdx.x;
    __shared__ unsigned sm[256];
    unsigned m = 0u;
    for (int i = tid; i < nblk; i += 256) {
        unsigned v = g_bmax[row * MAXBLK + i];
        if (v > m) m = v;
    }
    sm[tid] = m;
    __syncthreads();
    for (int o = 128; o; o >>= 1) {
        if (tid < o) { if (sm[tid + o] > sm[tid]) sm[tid] = sm[tid + o]; }
        __syncthreads();
    }
    if (tid == 0) {
        unsigned maxbin = sm[0] >> 5;           // quarter-octave bins
        unsigned tb = (maxbin > 4u) ? (maxbin - 4u) : 0u;  // threshold = max/2
        g_thr[row] = tb << 5;
    }
}

// ---------------- kernel: candidate collection, warp-aggregated + block-buffered ----------------
// ONE global atomic per block (plus rare overflow path) instead of one per candidate.
__global__ void __launch_bounds__(256)
k_filter(int N) {
    int row = blockIdx.x / SEGS2;
    int seg = blockIdx.x % SEGS2;
    int tid = threadIdx.x;
    int lane = tid & 31;
    unsigned thr = g_thr[row];

    __shared__ int s_cnt;
    __shared__ int s_base, s_tot;
    __shared__ int s_buf[FBUF];
    if (tid == 0) s_cnt = 0;
    __syncthreads();

    int chunk = (((N + SEGS2 - 1) / SEGS2) + 7) & ~7;   // multiple of 8
    int s0 = seg * chunk;
    int s1 = s0 + chunk; if (s1 > N) s1 = N;
    const unsigned short* S = g_sbf + (size_t)row * N;

    if (s0 < N) {
        const uint4* S4 = reinterpret_cast<const uint4*>(S + s0);   // s0 multiple of 8
        int n4 = (s1 - s0) >> 3;
        int iters = (n4 + 255) >> 8;          // block-uniform trip count
        for (int it = 0; it < iters; ++it) {
            int i4 = it * 256 + tid;
            unsigned m8 = 0;
            uint4 x = make_uint4(0u, 0u, 0u, 0u);
            if (i4 < n4) {
                x = S4[i4];
                m8 |= (map16(x.x & 0xFFFFu) >= thr) ? 1u   : 0u;
                m8 |= (map16(x.x >> 16)     >= thr) ? 2u   : 0u;
                m8 |= (map16(x.y & 0xFFFFu) >= thr) ? 4u   : 0u;
                m8 |= (map16(x.y >> 16)     >= thr) ? 8u   : 0u;
                m8 |= (map16(x.z & 0xFFFFu) >= thr) ? 16u  : 0u;
                m8 |= (map16(x.z >> 16)     >= thr) ? 32u  : 0u;
                m8 |= (map16(x.w & 0xFFFFu) >= thr) ? 64u  : 0u;
                m8 |= (map16(x.w >> 16)     >= thr) ? 128u : 0u;
            }
            int mc = __popc(m8);
            // warp inclusive scan -> exclusive prefix
            int pfx = mc;
#pragma unroll
            for (int o = 1; o < 32; o <<= 1) {
                int v = __shfl_up_sync(FULLMASK, pfx, o);
                if (lane >= o) pfx += v;
            }
            int wtot = __shfl_sync(FULLMASK, pfx, 31);
            int excl = pfx - mc;
            int base = 0;
            if (lane == 0 && wtot) base = atomicAdd(&s_cnt, wtot);
            base = __shfl_sync(FULLMASK, base, 0);
            int p = base + excl;
            int e0 = s0 + (i4 << 3);
            while (m8) {
                int b = __ffs((int)m8) - 1; m8 &= m8 - 1;
                int idx = e0 + b;
                if (p < FBUF) {
                    s_buf[p] = idx;
                } else {    // overflow fallback (statistically never taken)
                    int gp = atomicAdd(&g_cnt[row], 1);
                    if (gp < CAP) g_ci[row * CAP + gp] = idx;
                }
                ++p;
            }
        }
        // scalar tail (s1 not multiple of 8 — last segment only)
        int tail0 = s0 + (n4 << 3);
        for (int q = tail0 + tid; q < s1; q += 256) {
            if (map16(S[q]) >= thr) {
                int gp = atomicAdd(&g_cnt[row], 1);
                if (gp < CAP) g_ci[row * CAP + gp] = q;
            }
        }
    }
    __syncthreads();
    if (tid == 0) {
        int tot = s_cnt; if (tot > FBUF) tot = FBUF;
        s_tot = tot;
        s_base = tot ? atomicAdd(&g_cnt[row], tot) : 0;
    }
    __syncthreads();
    for (int i = tid; i < s_tot; i += 256) {
        int pos = s_base + i;
        if (pos < CAP) g_ci[row * CAP + pos] = s_buf[i];
    }
}

// ---------------- kernel: exact fp32 rescore of candidates ----------------
__global__ void __launch_bounds__(256)
k_rescore(const float* __restrict__ keys) {
    int row = blockIdx.x / RSEG;
    int seg = blockIdx.x % RSEG;
    int w = threadIdx.x >> 5, lane = threadIdx.x & 31;
    int cnt = g_cnt[row]; if (cnt > CAP) cnt = CAP;
    const float* q = g_query + row * DIM;

    for (int c = seg * 8 + w; c < cnt; c += 8 * RSEG) {
        int idx = g_ci[row * CAP + c];
        const float* kp = keys + (size_t)idx * DIM;
        float s = 0.f;
#pragma unroll
        for (int j = 0; j < 4; ++j) {
            float4 kv = *reinterpret_cast<const float4*>(kp + lane * 16 + j * 4);
            float4 qv = *reinterpret_cast<const float4*>(q + lane * 16 + j * 4);
            s += kv.x * qv.x + kv.y * qv.y + kv.z * qv.z + kv.w * qv.w;
        }
#pragma unroll
        for (int o = 16; o; o >>= 1) s += __shfl_xor_sync(FULLMASK, s, o);
        if (lane == 0) g_cv[row * CAP + c] = s * SCALE_D;
    }
}

// ---------------- warp helpers for exact merge ----------------
__device__ __forceinline__ float warp_min32(float v) {
#pragma unroll
    for (int o = 16; o; o >>= 1) v = fminf(v, __shfl_xor_sync(FULLMASK, v, o));
    return v;
}

__device__ __forceinline__ void topk_insert4(float a0, float a1, float a2, float a3,
                                             int base, float& v0, float& v1,
                                             int& i0, int& i1, float& thr) {
    unsigned pm = (unsigned)(a0 > thr) | ((unsigned)(a1 > thr) << 1) |
                  ((unsigned)(a2 > thr) << 2) | ((unsigned)(a3 > thr) << 3);
    while (__any_sync(FULLMASK, pm != 0)) {
        int c = __ffs(pm) - 1;
        float cv = (c == 0) ? a0 : (c == 1) ? a1 : (c == 2) ? a2 : a3;
        int ci = base + c;
        unsigned ball = __ballot_sync(FULLMASK, pm != 0);
        int src = __ffs(ball) - 1;
        float cand = __shfl_sync(FULLMASK, cv, src);
        int candi = __shfl_sync(FULLMASK, ci, src);
        int lane = threadIdx.x & 31;
        if (lane == src) pm &= pm - 1;
        if (cand > thr) {
            float mn = fminf(v0, v1);
            float wmn = warp_min32(mn);
            unsigned who = __ballot_sync(FULLMASK, mn == wmn);
            int wl = __ffs(who) - 1;
            if (lane == wl) {
                if (v0 <= v1) { v0 = cand; i0 = candi; }
                else          { v1 = cand; i1 = candi; }
            }
            thr = warp_min32(fminf(v0, v1));
        }
        if (pm) {
            if ((pm & 1u) && a0 <= thr) pm &= ~1u;
            if ((pm & 2u) && a1 <= thr) pm &= ~2u;
            if ((pm & 4u) && a2 <= thr) pm &= ~4u;
            if ((pm & 8u) && a3 <= thr) pm &= ~8u;
        }
    }
}

// ---------------- kernel: exact sorted top-64 from candidates (256 threads) ----------------
__global__ void __launch_bounds__(256)
k_topk_merge() {
    int row = blockIdx.x;
    int tid = threadIdx.x;
    int lane = tid & 31;
    int wid = tid >> 5;

    int C = g_cnt[row]; if (C > CAP) C = CAP;
    const float* CV = g_cv + (size_t)row * CAP;
    const int*   CI = g_ci + (size_t)row * CAP;

    float v0 = NEG_BIG, v1 = NEG_BIG;
    int i0 = 0, i1 = 0;
    float thr = NEG_BIG;

    int iters = (C + 1023) >> 10;            // 256 threads x 4 per iter
    for (int it = 0; it < iters; ++it) {
        int f = (it << 10) + (tid << 2);
        float a0 = (f + 0 < C) ? CV[f + 0] : NEG_BIG;
        float a1 = (f + 1 < C) ? CV[f + 1] : NEG_BIG;
        float a2 = (f + 2 < C) ? CV[f + 2] : NEG_BIG;
        float a3 = (f + 3 < C) ? CV[f + 3] : NEG_BIG;
        topk_insert4(a0, a1, a2, a3, f, v0, v1, i0, i1, thr);
    }
    i0 = (v0 > NEG_BIG) ? CI[i0] : 0x7fffffff;
    i1 = (v1 > NEG_BIG) ? CI[i1] : 0x7fffffff;

    __shared__ float sv[512];
    __shared__ int   si[512];
    __shared__ float wv[8];
    __shared__ int   wp[8];
    __shared__ int   wsrc[8];
    sv[wid * 64 + lane]      = v0;  si[wid * 64 + lane]      = i0;
    sv[wid * 64 + 32 + lane] = v1;  si[wid * 64 + 32 + lane] = i1;
    __syncthreads();

    for (int j = 0; j < MAXK; ++j) {
        float bv = sv[wid * 64 + lane];      int bi = si[wid * 64 + lane];      int bp = wid * 64 + lane;
        float ov = sv[wid * 64 + 32 + lane]; int oi = si[wid * 64 + 32 + lane]; int op = wid * 64 + 32 + lane;
        if (ov > bv || (ov == bv && oi < bi)) { bv = ov; bi = oi; bp = op; }
#pragma unroll
        for (int o = 16; o; o >>= 1) {
            float xv = __shfl_xor_sync(FULLMASK, bv, o);
            int   xi = __shfl_xor_sync(FULLMASK, bi, o);
            int   xp = __shfl_xor_sync(FULLMASK, bp, o);
            if (xv > bv || (xv == bv && xi < bi)) { bv = xv; bi = xi; bp = xp; }
        }
        if (lane == 0) { wv[wid] = bv; wp[wid] = bi; wsrc[wid] = bp; }
        __syncthreads();
        if (wid == 0) {
            float cv2 = (lane < 8) ? wv[lane] : NEG_BIG;
            int   ci2 = (lane < 8) ? wp[lane] : 0x7fffffff;
            int   cp2 = (lane < 8) ? wsrc[lane] : 0;
#pragma unroll
            for (int o = 4; o; o >>= 1) {
                float xv = __shfl_xor_sync(FULLMASK, cv2, o);
                int   xi = __shfl_xor_sync(FULLMASK, ci2, o);
                int   xp = __shfl_xor_sync(FULLMASK, cp2, o);
                if (xv > cv2 || (xv == cv2 && xi < ci2)) { cv2 = xv; ci2 = xi; cp2 = xp; }
            }
            if (lane == 0) {
                g_topv[row * MAXK + j] = cv2;
                g_topi[row * MAXK + j] = ci2;
                sv[cp2] = NEG_BIG;
                si[cp2] = 0x7fffffff;
            }
        }
        __syncthreads();
    }
}

// ---------------- kernel: softmax(top-kd) + gather + weighted sum ----------------
__global__ void k_aggregate(const float* __restrict__ P,
                            const int* __restrict__ kdyn,
                            float* __restrict__ out) {
    int row = blockIdx.x;
    int tid = threadIdx.x;
    __shared__ float ws[MAXK];
    __shared__ int   idx[MAXK];
    __shared__ float s_inv;

    int kd = *kdyn;
    kd = kd < 0 ? 0 : (kd > MAXK ? MAXK : kd);

    if (tid < MAXK) {
        float v = g_topv[row * MAXK + tid];
        idx[tid] = g_topi[row * MAXK + tid];
        float m = (kd > 0) ? g_topv[row * MAXK] : -1e9f;
        float mv = (tid < kd) ? v : -1e9f;
        ws[tid] = expf(mv - m);
    }
    __syncthreads();
    if (tid == 0) {
        float s = 0.f;
#pragma unroll
        for (int j = 0; j < MAXK; ++j) s += ws[j];
        s_inv = 1.0f / s;
    }
    __syncthreads();

    float a = 0.f;
#pragma unroll 4
    for (int j = 0; j < MAXK; ++j) {
        float w = ws[j];
        if (w != 0.f) a += w * P[(size_t)idx[j] * DIM + tid];
    }
    out[row * DIM + tid] = a * s_inv;
}

// ---------------- launcher ----------------
extern "C" void kernel_launch(void* const* d_in, const int* in_sizes, int n_in,
                              void* d_out, int out_size) {
    const float* hidden      = (const float*)d_in[0];
    const float* pool_params = (const float*)d_in[1];
    const float* pool_keys   = (const float*)d_in[2];
    const float* W           = (const float*)d_in[3];
    const float* bias        = (const float*)d_in[4];
    const int*   k_dynamic   = (const int*)d_in[5];
    float* out = (float*)d_out;

    int N = in_sizes[2] / DIM;

    static const size_t SMEMTC = (size_t)(BATCH * QS + TCN * KS) * sizeof(__nv_bfloat16);
    cudaFuncSetAttribute(k_scores_tc, cudaFuncAttributeMaxDynamicSharedMemorySize, (int)SMEMTC);

    int nblk = (N + TCN - 1) / TCN;
    if (nblk > MAXBLK) nblk = MAXBLK;

    k_pool_partial<<<BATCH * 8, 256>>>(hidden);               // 0
    k_query<<<BATCH, DIM>>>(W, bias);                         // 1
    k_zero32<<<1, 32>>>();                                    // 2
    k_scores_tc<<<nblk, 256, SMEMTC>>>(pool_keys, N);         // 3  <-- profile slot
    k_rowmax<<<BATCH, 256>>>(nblk);                           // 4
    k_filter<<<BATCH * SEGS2, 256>>>(N);                      // 5
    k_rescore<<<BATCH * RSEG, 256>>>(pool_keys);              // 6
    k_topk_merge<<<BATCH, 256>>>();                           // 7
    k_aggregate<<<BATCH, DIM>>>(pool_params, k_dynamic, out); // 8
}

// round 13
// speedup vs baseline: 1.9250x; 1.1031x over previous
#include <cuda_runtime.h>
#include <cuda_bf16.h>

// Problem constants (fixed by setup_inputs)
#define BATCH 32
#define TSEQ  1024
#define DIM   512
#define NMAX  500000
#define MAXK  64

#define FULLMASK 0xffffffffu
#define NEG_BIG (-3.0e38f)

#define SEGS2 32
#define RSEG  64
#define CAP   16384
#define MAXBLK 2048
#define FBUF  2048

// tensor-core scores tiling
#define TCN 256        // keys per block
#define KC  64         // k-chunk
#define KS  72         // key row stride in bf16
#define QS  520        // query row stride in bf16

#define SCALE_D 0.044194173824159216f  // 1/sqrt(512)

// ---------------- device scratch (no allocations allowed) ----------------
__device__ float          g_part[BATCH * 8 * DIM];
__device__ float          g_query[BATCH * DIM];
__device__ unsigned short g_sbf[(size_t)BATCH * NMAX];   // approx scores, bf16 bits (32 MB)
__device__ unsigned       g_bmax[BATCH * MAXBLK];        // per-(row, score-block) max (mapped u16)
__device__ unsigned       g_thr[BATCH];
__device__ int            g_cnt[BATCH];
__device__ float          g_cv[BATCH * CAP];
__device__ int            g_ci[BATCH * CAP];
__device__ float          g_topv[BATCH * MAXK];
__device__ int            g_topi[BATCH * MAXK];

// monotone map on bf16 bit pattern: a > b (as floats) <=> map16(a) > map16(b)
__device__ __forceinline__ unsigned map16(unsigned u) {
    unsigned s = u >> 15;
    return (u ^ (0x8000u | (0x7FFFu & (0u - s)))) & 0xFFFFu;
}

// ---------------- kernel: partial mean over T (256 blocks — full-chip) ----------------
__global__ void k_pool_partial(const float* __restrict__ hidden) {
    int b = blockIdx.x >> 3;
    int chunk = blockIdx.x & 7;
    int tid = threadIdx.x;
    const float* base = hidden + ((size_t)b * TSEQ + chunk * 128) * DIM;
    float a0 = 0.f, a1 = 0.f;
#pragma unroll 4
    for (int t = 0; t < 128; ++t) {
        a0 += base[t * DIM + tid];
        a1 += base[t * DIM + tid + 256];
    }
    g_part[(b * 8 + chunk) * DIM + tid]       = a0;
    g_part[(b * 8 + chunk) * DIM + tid + 256] = a1;
}

// ---------------- kernel: query = mean @ W + b ----------------
__global__ void k_query(const float* __restrict__ W, const float* __restrict__ bias) {
    int b = blockIdx.x;
    int j = threadIdx.x;
    __shared__ float sp[DIM];
    float s = 0.f;
#pragma unroll
    for (int c = 0; c < 8; ++c) s += g_part[(b * 8 + c) * DIM + j];
    sp[j] = s * (1.0f / (float)TSEQ);
    __syncthreads();
    float q = bias[j];
#pragma unroll 8
    for (int d = 0; d < DIM; ++d) q += sp[d] * W[d * DIM + j];
    g_query[b * DIM + j] = q;
}

// ---------------- kernel: zero per-row counters (pads launch index) ----------------
__global__ void k_zero32() {
    if (threadIdx.x < BATCH) g_cnt[threadIdx.x] = 0;
}

// ---------------- mma.sync m16n8k16 bf16 wrapper ----------------
__device__ __forceinline__ void mma_bf16(float c[4],
                                         unsigned a0, unsigned a1, unsigned a2, unsigned a3,
                                         unsigned b0, unsigned b1) {
    asm volatile(
        "mma.sync.aligned.m16n8k16.row.col.f32.bf16.bf16.f32 "
        "{%0,%1,%2,%3}, {%4,%5,%6,%7}, {%8,%9}, {%0,%1,%2,%3};"
        : "+f"(c[0]), "+f"(c[1]), "+f"(c[2]), "+f"(c[3])
        : "r"(a0), "r"(a1), "r"(a2), "r"(a3), "r"(b0), "r"(b1));
}

__device__ __forceinline__ unsigned pack_bf16x2(float lo, float hi) {
    __nv_bfloat162 p = __floats2bfloat162_rn(lo, hi);
    return *reinterpret_cast<unsigned*>(&p);
}

// ---------------- kernel (PROFILE SLOT): approx scores via tensor cores ----------------
__global__ void __launch_bounds__(256, 2)
k_scores_tc(const float* __restrict__ keys, int N) {
    extern __shared__ __nv_bfloat16 sm[];
    __nv_bfloat16* qs = sm;              // [32][QS]
    __nv_bfloat16* ks = sm + BATCH * QS; // [TCN][KS]
    __shared__ unsigned srmax[BATCH];

    int tid = threadIdx.x;
    int w = tid >> 5, lane = tid & 31;
    int g = lane >> 2, tig = lane & 3;
    int n0 = blockIdx.x * TCN;

    if (tid < BATCH) srmax[tid] = 0u;

    // load queries fp32 -> bf16 smem
#pragma unroll
    for (int it = 0; it < 16; ++it) {
        int f = tid + it * 256;
        int row = f >> 7;
        int kq = f & 127;
        float4 v = *reinterpret_cast<const float4*>(&g_query[row * DIM + kq * 4]);
        unsigned p0 = pack_bf16x2(v.x, v.y);
        unsigned p1 = pack_bf16x2(v.z, v.w);
        unsigned long long pk = ((unsigned long long)p1 << 32) | p0;
        *reinterpret_cast<unsigned long long*>(&qs[row * QS + kq * 4]) = pk;
    }

    float acc[2][4][4];
#pragma unroll
    for (int mt = 0; mt < 2; ++mt)
#pragma unroll
        for (int nt = 0; nt < 4; ++nt)
#pragma unroll
            for (int r = 0; r < 4; ++r) acc[mt][nt][r] = 0.f;

    for (int kt = 0; kt < DIM / KC; ++kt) {
        __syncthreads();
#pragma unroll
        for (int it = 0; it < 16; ++it) {
            int f = tid + it * 256;
            int key = f >> 4;
            int kq = f & 15;
            int gk = n0 + key;
            float4 v = make_float4(0.f, 0.f, 0.f, 0.f);
            if (gk < N)
                v = *reinterpret_cast<const float4*>(&keys[(size_t)gk * DIM + kt * KC + kq * 4]);
            unsigned p0 = pack_bf16x2(v.x, v.y);
            unsigned p1 = pack_bf16x2(v.z, v.w);
            unsigned long long pk = ((unsigned long long)p1 << 32) | p0;
            *reinterpret_cast<unsigned long long*>(&ks[key * KS + kq * 4]) = pk;
        }
        __syncthreads();

#pragma unroll
        for (int s = 0; s < KC / 16; ++s) {
            int k0 = s * 16;
            unsigned a[2][4];
#pragma unroll
            for (int mt = 0; mt < 2; ++mt) {
                const __nv_bfloat16* alo = &qs[(mt * 16 + g) * QS + kt * KC + k0 + tig * 2];
                const __nv_bfloat16* ahi = alo + 8 * QS;
                a[mt][0] = *reinterpret_cast<const unsigned*>(alo);
                a[mt][1] = *reinterpret_cast<const unsigned*>(ahi);
                a[mt][2] = *reinterpret_cast<const unsigned*>(alo + 8);
                a[mt][3] = *reinterpret_cast<const unsigned*>(ahi + 8);
            }
#pragma unroll
            for (int nt = 0; nt < 4; ++nt) {
                const __nv_bfloat16* bp = &ks[(w * 32 + nt * 8 + g) * KS + k0 + tig * 2];
                unsigned b0 = *reinterpret_cast<const unsigned*>(bp);
                unsigned b1 = *reinterpret_cast<const unsigned*>(bp + 8);
                mma_bf16(acc[0][nt], a[0][0], a[0][1], a[0][2], a[0][3], b0, b1);
                mma_bf16(acc[1][nt], a[1][0], a[1][1], a[1][2], a[1][3], b0, b1);
            }
        }
    }

    // epilogue: scattered bf16 stores + per-row tile max
    unsigned mlo[2] = {0u, 0u}, mhi[2] = {0u, 0u};
#pragma unroll
    for (int mt = 0; mt < 2; ++mt) {
#pragma unroll
        for (int nt = 0; nt < 4; ++nt) {
            int row_lo = mt * 16 + g;
            int row_hi = row_lo + 8;
            int col = n0 + w * 32 + nt * 8 + tig * 2;
            if (col < N) {
                unsigned plo = pack_bf16x2(acc[mt][nt][0] * SCALE_D, acc[mt][nt][1] * SCALE_D);
                unsigned phi = pack_bf16x2(acc[mt][nt][2] * SCALE_D, acc[mt][nt][3] * SCALE_D);
                *reinterpret_cast<unsigned*>(&g_sbf[(size_t)row_lo * N + col]) = plo;
                *reinterpret_cast<unsigned*>(&g_sbf[(size_t)row_hi * N + col]) = phi;
                unsigned u;
                u = map16(plo & 0xFFFFu); if (u > mlo[mt]) mlo[mt] = u;
                u = map16(plo >> 16);     if (u > mlo[mt]) mlo[mt] = u;
                u = map16(phi & 0xFFFFu); if (u > mhi[mt]) mhi[mt] = u;
                u = map16(phi >> 16);     if (u > mhi[mt]) mhi[mt] = u;
            }
        }
    }
    __syncthreads();
#pragma unroll
    for (int mt = 0; mt < 2; ++mt) {
        atomicMax(&srmax[mt * 16 + g], mlo[mt]);
        atomicMax(&srmax[mt * 16 + 8 + g], mhi[mt]);
    }
    __syncthreads();
    if (tid < BATCH) g_bmax[tid * MAXBLK + blockIdx.x] = srmax[tid];
}

// ---------------- kernel: threshold = 64th-largest block max (sound), minus 2-bin margin ----------------
// Proof of safety: the 64 block maxima >= t are themselves 64 distinct score values >= t,
// so s64 >= t and every true top-64 element passes the filter.
__global__ void __launch_bounds__(256)
k_threshold(int nblk) {
    int row = blockIdx.x;
    int tid = threadIdx.x;
    __shared__ unsigned h[2048];
    for (int i = tid; i < 2048; i += 256) h[i] = 0u;
    __syncthreads();
    for (int i = tid; i < nblk; i += 256)
        atomicAdd(&h[g_bmax[row * MAXBLK + i] >> 5], 1u);
    __syncthreads();
    if (tid == 0) {
        int cum = 0;
        unsigned thr = 0u;
        for (int b = 2047; b >= 0; --b) {
            cum += (int)h[b];
            if (cum >= MAXK) {
                int bm = b - 2;            // bf16-vs-fp32 ordering margin (~17%)
                if (bm < 0) bm = 0;
                thr = (unsigned)bm << 5;
                break;
            }
        }
        g_thr[row] = thr;                  // stays 0 if nblk*? < 64 -> everything passes
    }
}

// ---------------- kernel: candidate collection, warp-aggregated + block-buffered ----------------
__global__ void __launch_bounds__(256)
k_filter(int N) {
    int row = blockIdx.x / SEGS2;
    int seg = blockIdx.x % SEGS2;
    int tid = threadIdx.x;
    int lane = tid & 31;
    unsigned thr = g_thr[row];

    __shared__ int s_cnt;
    __shared__ int s_base, s_tot;
    __shared__ int s_buf[FBUF];
    if (tid == 0) s_cnt = 0;
    __syncthreads();

    int chunk = (((N + SEGS2 - 1) / SEGS2) + 7) & ~7;   // multiple of 8
    int s0 = seg * chunk;
    int s1 = s0 + chunk; if (s1 > N) s1 = N;
    const unsigned short* S = g_sbf + (size_t)row * N;

    if (s0 < N) {
        const uint4* S4 = reinterpret_cast<const uint4*>(S + s0);   // s0 multiple of 8
        int n4 = (s1 - s0) >> 3;
        int iters = (n4 + 255) >> 8;          // block-uniform trip count
        for (int it = 0; it < iters; ++it) {
            int i4 = it * 256 + tid;
            unsigned m8 = 0;
            uint4 x = make_uint4(0u, 0u, 0u, 0u);
            if (i4 < n4) {
                x = S4[i4];
                m8 |= (map16(x.x & 0xFFFFu) >= thr) ? 1u   : 0u;
                m8 |= (map16(x.x >> 16)     >= thr) ? 2u   : 0u;
                m8 |= (map16(x.y & 0xFFFFu) >= thr) ? 4u   : 0u;
                m8 |= (map16(x.y >> 16)     >= thr) ? 8u   : 0u;
                m8 |= (map16(x.z & 0xFFFFu) >= thr) ? 16u  : 0u;
                m8 |= (map16(x.z >> 16)     >= thr) ? 32u  : 0u;
                m8 |= (map16(x.w & 0xFFFFu) >= thr) ? 64u  : 0u;
                m8 |= (map16(x.w >> 16)     >= thr) ? 128u : 0u;
            }
            int mc = __popc(m8);
            int pfx = mc;
#pragma unroll
            for (int o = 1; o < 32; o <<= 1) {
                int v = __shfl_up_sync(FULLMASK, pfx, o);
                if (lane >= o) pfx += v;
            }
            int wtot = __shfl_sync(FULLMASK, pfx, 31);
            int excl = pfx - mc;
            int base = 0;
            if (lane == 0 && wtot) base = atomicAdd(&s_cnt, wtot);
            base = __shfl_sync(FULLMASK, base, 0);
            int p = base + excl;
            int e0 = s0 + (i4 << 3);
            while (m8) {
                int b = __ffs((int)m8) - 1; m8 &= m8 - 1;
                int idx = e0 + b;
                if (p < FBUF) {
                    s_buf[p] = idx;
                } else {    // overflow fallback (statistically never taken)
                    int gp = atomicAdd(&g_cnt[row], 1);
                    if (gp < CAP) g_ci[row * CAP + gp] = idx;
                }
                ++p;
            }
        }
        // scalar tail (s1 not multiple of 8 — last segment only)
        int tail0 = s0 + (n4 << 3);
        for (int q = tail0 + tid; q < s1; q += 256) {
            if (map16(S[q]) >= thr) {
                int gp = atomicAdd(&g_cnt[row], 1);
                if (gp < CAP) g_ci[row * CAP + gp] = q;
            }
        }
    }
    __syncthreads();
    if (tid == 0) {
        int tot = s_cnt; if (tot > FBUF) tot = FBUF;
        s_tot = tot;
        s_base = tot ? atomicAdd(&g_cnt[row], tot) : 0;
    }
    __syncthreads();
    for (int i = tid; i < s_tot; i += 256) {
        int pos = s_base + i;
        if (pos < CAP) g_ci[row * CAP + pos] = s_buf[i];
    }
}

// ---------------- kernel: exact fp32 rescore of candidates ----------------
__global__ void __launch_bounds__(256)
k_rescore(const float* __restrict__ keys) {
    int row = blockIdx.x / RSEG;
    int seg = blockIdx.x % RSEG;
    int w = threadIdx.x >> 5, lane = threadIdx.x & 31;
    int cnt = g_cnt[row]; if (cnt > CAP) cnt = CAP;
    const float* q = g_query + row * DIM;

    for (int c = seg * 8 + w; c < cnt; c += 8 * RSEG) {
        int idx = g_ci[row * CAP + c];
        const float* kp = keys + (size_t)idx * DIM;
        float s = 0.f;
#pragma unroll
        for (int j = 0; j < 4; ++j) {
            float4 kv = *reinterpret_cast<const float4*>(kp + lane * 16 + j * 4);
            float4 qv = *reinterpret_cast<const float4*>(q + lane * 16 + j * 4);
            s += kv.x * qv.x + kv.y * qv.y + kv.z * qv.z + kv.w * qv.w;
        }
#pragma unroll
        for (int o = 16; o; o >>= 1) s += __shfl_xor_sync(FULLMASK, s, o);
        if (lane == 0) g_cv[row * CAP + c] = s * SCALE_D;
    }
}

// ---------------- warp helpers for exact merge ----------------
__device__ __forceinline__ float warp_min32(float v) {
#pragma unroll
    for (int o = 16; o; o >>= 1) v = fminf(v, __shfl_xor_sync(FULLMASK, v, o));
    return v;
}

__device__ __forceinline__ void topk_insert4(float a0, float a1, float a2, float a3,
                                             int base, float& v0, float& v1,
                                             int& i0, int& i1, float& thr) {
    unsigned pm = (unsigned)(a0 > thr) | ((unsigned)(a1 > thr) << 1) |
                  ((unsigned)(a2 > thr) << 2) | ((unsigned)(a3 > thr) << 3);
    while (__any_sync(FULLMASK, pm != 0)) {
        int c = __ffs(pm) - 1;
        float cv = (c == 0) ? a0 : (c == 1) ? a1 : (c == 2) ? a2 : a3;
        int ci = base + c;
        unsigned ball = __ballot_sync(FULLMASK, pm != 0);
        int src = __ffs(ball) - 1;
        float cand = __shfl_sync(FULLMASK, cv, src);
        int candi = __shfl_sync(FULLMASK, ci, src);
        int lane = threadIdx.x & 31;
        if (lane == src) pm &= pm - 1;
        if (cand > thr) {
            float mn = fminf(v0, v1);
            float wmn = warp_min32(mn);
            unsigned who = __ballot_sync(FULLMASK, mn == wmn);
            int wl = __ffs(who) - 1;
            if (lane == wl) {
                if (v0 <= v1) { v0 = cand; i0 = candi; }
                else          { v1 = cand; i1 = candi; }
            }
            thr = warp_min32(fminf(v0, v1));
        }
        if (pm) {
            if ((pm & 1u) && a0 <= thr) pm &= ~1u;
            if ((pm & 2u) && a1 <= thr) pm &= ~2u;
            if ((pm & 4u) && a2 <= thr) pm &= ~4u;
            if ((pm & 8u) && a3 <= thr) pm &= ~8u;
        }
    }
}

// ---------------- kernel: exact sorted top-64 from candidates (256 threads) ----------------
__global__ void __launch_bounds__(256)
k_topk_merge() {
    int row = blockIdx.x;
    int tid = threadIdx.x;
    int lane = tid & 31;
    int wid = tid >> 5;

    int C = g_cnt[row]; if (C > CAP) C = CAP;
    const float* CV = g_cv + (size_t)row * CAP;
    const int*   CI = g_ci + (size_t)row * CAP;

    float v0 = NEG_BIG, v1 = NEG_BIG;
    int i0 = 0, i1 = 0;
    float thr = NEG_BIG;

    int iters = (C + 1023) >> 10;            // 256 threads x 4 per iter
    for (int it = 0; it < iters; ++it) {
        int f = (it << 10) + (tid << 2);
        float a0 = (f + 0 < C) ? CV[f + 0] : NEG_BIG;
        float a1 = (f + 1 < C) ? CV[f + 1] : NEG_BIG;
        float a2 = (f + 2 < C) ? CV[f + 2] : NEG_BIG;
        float a3 = (f + 3 < C) ? CV[f + 3] : NEG_BIG;
        topk_insert4(a0, a1, a2, a3, f, v0, v1, i0, i1, thr);
    }
    i0 = (v0 > NEG_BIG) ? CI[i0] : 0x7fffffff;
    i1 = (v1 > NEG_BIG) ? CI[i1] : 0x7fffffff;

    __shared__ float sv[512];
    __shared__ int   si[512];
    __shared__ float wv[8];
    __shared__ int   wp[8];
    __shared__ int   wsrc[8];
    sv[wid * 64 + lane]      = v0;  si[wid * 64 + lane]      = i0;
    sv[wid * 64 + 32 + lane] = v1;  si[wid * 64 + 32 + lane] = i1;
    __syncthreads();

    for (int j = 0; j < MAXK; ++j) {
        float bv = sv[wid * 64 + lane];      int bi = si[wid * 64 + lane];      int bp = wid * 64 + lane;
        float ov = sv[wid * 64 + 32 + lane]; int oi = si[wid * 64 + 32 + lane]; int op = wid * 64 + 32 + lane;
        if (ov > bv || (ov == bv && oi < bi)) { bv = ov; bi = oi; bp = op; }
#pragma unroll
        for (int o = 16; o; o >>= 1) {
            float xv = __shfl_xor_sync(FULLMASK, bv, o);
            int   xi = __shfl_xor_sync(FULLMASK, bi, o);
            int   xp = __shfl_xor_sync(FULLMASK, bp, o);
            if (xv > bv || (xv == bv && xi < bi)) { bv = xv; bi = xi; bp = xp; }
        }
        if (lane == 0) { wv[wid] = bv; wp[wid] = bi; wsrc[wid] = bp; }
        __syncthreads();
        if (wid == 0) {
            float cv2 = (lane < 8) ? wv[lane] : NEG_BIG;
            int   ci2 = (lane < 8) ? wp[lane] : 0x7fffffff;
            int   cp2 = (lane < 8) ? wsrc[lane] : 0;
#pragma unroll
            for (int o = 4; o; o >>= 1) {
                float xv = __shfl_xor_sync(FULLMASK, cv2, o);
                int   xi = __shfl_xor_sync(FULLMASK, ci2, o);
                int   xp = __shfl_xor_sync(FULLMASK, cp2, o);
                if (xv > cv2 || (xv == cv2 && xi < ci2)) { cv2 = xv; ci2 = xi; cp2 = xp; }
            }
            if (lane == 0) {
                g_topv[row * MAXK + j] = cv2;
                g_topi[row * MAXK + j] = ci2;
                sv[cp2] = NEG_BIG;
                si[cp2] = 0x7fffffff;
            }
        }
        __syncthreads();
    }
}

// ---------------- kernel: softmax(top-kd) + gather + weighted sum ----------------
__global__ void k_aggregate(const float* __restrict__ P,
                            const int* __restrict__ kdyn,
                            float* __restrict__ out) {
    int row = blockIdx.x;
    int tid = threadIdx.x;
    __shared__ float ws[MAXK];
    __shared__ int   idx[MAXK];
    __shared__ float s_inv;

    int kd = *kdyn;
    kd = kd < 0 ? 0 : (kd > MAXK ? MAXK : kd);

    if (tid < MAXK) {
        float v = g_topv[row * MAXK + tid];
        idx[tid] = g_topi[row * MAXK + tid];
        float m = (kd > 0) ? g_topv[row * MAXK] : -1e9f;
        float mv = (tid < kd) ? v : -1e9f;
        ws[tid] = expf(mv - m);
    }
    __syncthreads();
    if (tid == 0) {
        float s = 0.f;
#pragma unroll
        for (int j = 0; j < MAXK; ++j) s += ws[j];
        s_inv = 1.0f / s;
    }
    __syncthreads();

    float a = 0.f;
#pragma unroll 4
    for (int j = 0; j < MAXK; ++j) {
        float w = ws[j];
        if (w != 0.f) a += w * P[(size_t)idx[j] * DIM + tid];
    }
    out[row * DIM + tid] = a * s_inv;
}

// ---------------- launcher ----------------
extern "C" void kernel_launch(void* const* d_in, const int* in_sizes, int n_in,
                              void* d_out, int out_size) {
    const float* hidden      = (const float*)d_in[0];
    const float* pool_params = (const float*)d_in[1];
    const float* pool_keys   = (const float*)d_in[2];
    const float* W           = (const float*)d_in[3];
    const float* bias        = (const float*)d_in[4];
    const int*   k_dynamic   = (const int*)d_in[5];
    float* out = (float*)d_out;

    int N = in_sizes[2] / DIM;

    static const size_t SMEMTC = (size_t)(BATCH * QS + TCN * KS) * sizeof(__nv_bfloat16);
    cudaFuncSetAttribute(k_scores_tc, cudaFuncAttributeMaxDynamicSharedMemorySize, (int)SMEMTC);

    int nblk = (N + TCN - 1) / TCN;
    if (nblk > MAXBLK) nblk = MAXBLK;

    k_pool_partial<<<BATCH * 8, 256>>>(hidden);               // 0
    k_query<<<BATCH, DIM>>>(W, bias);                         // 1
    k_zero32<<<1, 32>>>();                                    // 2
    k_scores_tc<<<nblk, 256, SMEMTC>>>(pool_keys, N);         // 3  <-- profile slot
    k_threshold<<<BATCH, 256>>>(nblk);                        // 4
    k_filter<<<BATCH * SEGS2, 256>>>(N);                      // 5
    k_rescore<<<BATCH * RSEG, 256>>>(pool_keys);              // 6
    k_topk_merge<<<BATCH, 256>>>();                           // 7
    k_aggregate<<<BATCH, DIM>>>(pool_params, k_dynamic, out); // 8
}

// round 16
// speedup vs baseline: 2.2300x; 1.1584x over previous
#include <cuda_runtime.h>
#include <cuda_bf16.h>

// Problem constants (fixed by setup_inputs)
#define BATCH 32
#define TSEQ  1024
#define DIM   512
#define NMAX  500000
#define MAXK  64

#define FULLMASK 0xffffffffu
#define NEG_BIG (-3.0e38f)

#define MAXBLK 2048
#define SCAP   4096      // candidate capacity per row (expected ~350 with exact threshold)

// tensor-core scores tiling
#define TCN 256        // keys per block
#define KC  64         // k-chunk
#define KS  72         // key row stride in bf16
#define QS  520        // query row stride in bf16

#define SCALE_D 0.044194173824159216f  // 1/sqrt(512)

// ---------------- device scratch (no allocations allowed) ----------------
__device__ float          g_part[BATCH * 8 * DIM];
__device__ float          g_query[BATCH * DIM];
__device__ unsigned short g_sbf[(size_t)BATCH * NMAX];   // approx scores, bf16 bits (32 MB)
__device__ unsigned       g_bmax[BATCH * MAXBLK];        // per-(row, score-block) max (mapped u16)

// monotone map on bf16 bit pattern: a > b (as floats) <=> map16(a) > map16(b)
__device__ __forceinline__ unsigned map16(unsigned u) {
    unsigned s = u >> 15;
    return (u ^ (0x8000u | (0x7FFFu & (0u - s)))) & 0xFFFFu;
}

// ---------------- kernel: partial mean over T (256 blocks — full-chip) ----------------
__global__ void k_pool_partial(const float* __restrict__ hidden) {
    int b = blockIdx.x >> 3;
    int chunk = blockIdx.x & 7;
    int tid = threadIdx.x;
    const float* base = hidden + ((size_t)b * TSEQ + chunk * 128) * DIM;
    float a0 = 0.f, a1 = 0.f;
#pragma unroll 4
    for (int t = 0; t < 128; ++t) {
        a0 += base[t * DIM + tid];
        a1 += base[t * DIM + tid + 256];
    }
    g_part[(b * 8 + chunk) * DIM + tid]       = a0;
    g_part[(b * 8 + chunk) * DIM + tid + 256] = a1;
}

// ---------------- kernel: query = mean @ W + b ----------------
__global__ void k_query(const float* __restrict__ W, const float* __restrict__ bias) {
    int b = blockIdx.x;
    int j = threadIdx.x;
    __shared__ float sp[DIM];
    float s = 0.f;
#pragma unroll
    for (int c = 0; c < 8; ++c) s += g_part[(b * 8 + c) * DIM + j];
    sp[j] = s * (1.0f / (float)TSEQ);
    __syncthreads();
    float q = bias[j];
#pragma unroll 8
    for (int d = 0; d < DIM; ++d) q += sp[d] * W[d * DIM + j];
    g_query[b * DIM + j] = q;
}

// ---------------- mma.sync m16n8k16 bf16 wrapper ----------------
__device__ __forceinline__ void mma_bf16(float c[4],
                                         unsigned a0, unsigned a1, unsigned a2, unsigned a3,
                                         unsigned b0, unsigned b1) {
    asm volatile(
        "mma.sync.aligned.m16n8k16.row.col.f32.bf16.bf16.f32 "
        "{%0,%1,%2,%3}, {%4,%5,%6,%7}, {%8,%9}, {%0,%1,%2,%3};"
        : "+f"(c[0]), "+f"(c[1]), "+f"(c[2]), "+f"(c[3])
        : "r"(a0), "r"(a1), "r"(a2), "r"(a3), "r"(b0), "r"(b1));
}

__device__ __forceinline__ unsigned pack_bf16x2(float lo, float hi) {
    __nv_bfloat162 p = __floats2bfloat162_rn(lo, hi);
    return *reinterpret_cast<unsigned*>(&p);
}

// ---------------- kernel: approx scores via tensor cores + per-tile row max ----------------
__global__ void __launch_bounds__(256, 2)
k_scores_tc(const float* __restrict__ keys, int N) {
    extern __shared__ __nv_bfloat16 sm[];
    __nv_bfloat16* qs = sm;              // [32][QS]
    __nv_bfloat16* ks = sm + BATCH * QS; // [TCN][KS]
    __shared__ unsigned srmax[BATCH];

    int tid = threadIdx.x;
    int w = tid >> 5, lane = tid & 31;
    int g = lane >> 2, tig = lane & 3;
    int n0 = blockIdx.x * TCN;

    if (tid < BATCH) srmax[tid] = 0u;

    // load queries fp32 -> bf16 smem
#pragma unroll
    for (int it = 0; it < 16; ++it) {
        int f = tid + it * 256;
        int row = f >> 7;
        int kq = f & 127;
        float4 v = *reinterpret_cast<const float4*>(&g_query[row * DIM + kq * 4]);
        unsigned p0 = pack_bf16x2(v.x, v.y);
        unsigned p1 = pack_bf16x2(v.z, v.w);
        unsigned long long pk = ((unsigned long long)p1 << 32) | p0;
        *reinterpret_cast<unsigned long long*>(&qs[row * QS + kq * 4]) = pk;
    }

    float acc[2][4][4];
#pragma unroll
    for (int mt = 0; mt < 2; ++mt)
#pragma unroll
        for (int nt = 0; nt < 4; ++nt)
#pragma unroll
            for (int r = 0; r < 4; ++r) acc[mt][nt][r] = 0.f;

    for (int kt = 0; kt < DIM / KC; ++kt) {
        __syncthreads();
#pragma unroll
        for (int it = 0; it < 16; ++it) {
            int f = tid + it * 256;
            int key = f >> 4;
            int kq = f & 15;
            int gk = n0 + key;
            float4 v = make_float4(0.f, 0.f, 0.f, 0.f);
            if (gk < N)
                v = *reinterpret_cast<const float4*>(&keys[(size_t)gk * DIM + kt * KC + kq * 4]);
            unsigned p0 = pack_bf16x2(v.x, v.y);
            unsigned p1 = pack_bf16x2(v.z, v.w);
            unsigned long long pk = ((unsigned long long)p1 << 32) | p0;
            *reinterpret_cast<unsigned long long*>(&ks[key * KS + kq * 4]) = pk;
        }
        __syncthreads();

#pragma unroll
        for (int s = 0; s < KC / 16; ++s) {
            int k0 = s * 16;
            unsigned a[2][4];
#pragma unroll
            for (int mt = 0; mt < 2; ++mt) {
                const __nv_bfloat16* alo = &qs[(mt * 16 + g) * QS + kt * KC + k0 + tig * 2];
                const __nv_bfloat16* ahi = alo + 8 * QS;
                a[mt][0] = *reinterpret_cast<const unsigned*>(alo);
                a[mt][1] = *reinterpret_cast<const unsigned*>(ahi);
                a[mt][2] = *reinterpret_cast<const unsigned*>(alo + 8);
                a[mt][3] = *reinterpret_cast<const unsigned*>(ahi + 8);
            }
#pragma unroll
            for (int nt = 0; nt < 4; ++nt) {
                const __nv_bfloat16* bp = &ks[(w * 32 + nt * 8 + g) * KS + k0 + tig * 2];
                unsigned b0 = *reinterpret_cast<const unsigned*>(bp);
                unsigned b1 = *reinterpret_cast<const unsigned*>(bp + 8);
                mma_bf16(acc[0][nt], a[0][0], a[0][1], a[0][2], a[0][3], b0, b1);
                mma_bf16(acc[1][nt], a[1][0], a[1][1], a[1][2], a[1][3], b0, b1);
            }
        }
    }

    // epilogue: scattered bf16 stores + per-row tile max
    unsigned mlo[2] = {0u, 0u}, mhi[2] = {0u, 0u};
#pragma unroll
    for (int mt = 0; mt < 2; ++mt) {
#pragma unroll
        for (int nt = 0; nt < 4; ++nt) {
            int row_lo = mt * 16 + g;
            int row_hi = row_lo + 8;
            int col = n0 + w * 32 + nt * 8 + tig * 2;
            if (col < N) {
                unsigned plo = pack_bf16x2(acc[mt][nt][0] * SCALE_D, acc[mt][nt][1] * SCALE_D);
                unsigned phi = pack_bf16x2(acc[mt][nt][2] * SCALE_D, acc[mt][nt][3] * SCALE_D);
                *reinterpret_cast<unsigned*>(&g_sbf[(size_t)row_lo * N + col]) = plo;
                *reinterpret_cast<unsigned*>(&g_sbf[(size_t)row_hi * N + col]) = phi;
                unsigned u;
                u = map16(plo & 0xFFFFu); if (u > mlo[mt]) mlo[mt] = u;
                u = map16(plo >> 16);     if (u > mlo[mt]) mlo[mt] = u;
                u = map16(phi & 0xFFFFu); if (u > mhi[mt]) mhi[mt] = u;
                u = map16(phi >> 16);     if (u > mhi[mt]) mhi[mt] = u;
            }
        }
    }
    __syncthreads();
#pragma unroll
    for (int mt = 0; mt < 2; ++mt) {
        atomicMax(&srmax[mt * 16 + g], mlo[mt]);
        atomicMax(&srmax[mt * 16 + 8 + g], mhi[mt]);
    }
    __syncthreads();
    if (tid < BATCH) g_bmax[tid * MAXBLK + blockIdx.x] = srmax[tid];
}

// ---------------- warp helpers for exact merge ----------------
__device__ __forceinline__ float warp_min32(float v) {
#pragma unroll
    for (int o = 16; o; o >>= 1) v = fminf(v, __shfl_xor_sync(FULLMASK, v, o));
    return v;
}

__device__ __forceinline__ void topk_insert4(float a0, float a1, float a2, float a3,
                                             int base, float& v0, float& v1,
                                             int& i0, int& i1, float& thr) {
    unsigned pm = (unsigned)(a0 > thr) | ((unsigned)(a1 > thr) << 1) |
                  ((unsigned)(a2 > thr) << 2) | ((unsigned)(a3 > thr) << 3);
    while (__any_sync(FULLMASK, pm != 0)) {
        int c = __ffs(pm) - 1;
        float cv = (c == 0) ? a0 : (c == 1) ? a1 : (c == 2) ? a2 : a3;
        int ci = base + c;
        unsigned ball = __ballot_sync(FULLMASK, pm != 0);
        int src = __ffs(ball) - 1;
        float cand = __shfl_sync(FULLMASK, cv, src);
        int candi = __shfl_sync(FULLMASK, ci, src);
        int lane = threadIdx.x & 31;
        if (lane == src) pm &= pm - 1;
        if (cand > thr) {
            float mn = fminf(v0, v1);
            float wmn = warp_min32(mn);
            unsigned who = __ballot_sync(FULLMASK, mn == wmn);
            int wl = __ffs(who) - 1;
            if (lane == wl) {
                if (v0 <= v1) { v0 = cand; i0 = candi; }
                else          { v1 = cand; i1 = candi; }
            }
            thr = warp_min32(fminf(v0, v1));
        }
        if (pm) {
            if ((pm & 1u) && a0 <= thr) pm &= ~1u;
            if ((pm & 2u) && a1 <= thr) pm &= ~2u;
            if ((pm & 4u) && a2 <= thr) pm &= ~4u;
            if ((pm & 8u) && a3 <= thr) pm &= ~8u;
        }
    }
}

// ---------------- kernel (PROFILE SLOT): fused threshold+filter+rescore+merge+aggregate ----------------
// grid = BATCH (one block per row), 512 threads (16 warps).
__global__ void __launch_bounds__(512)
k_select(const float* __restrict__ keys, const float* __restrict__ P,
         const int* __restrict__ kdyn, float* __restrict__ out, int N, int nblk) {
    int row = blockIdx.x;
    int tid = threadIdx.x;
    int lane = tid & 31;
    int wid = tid >> 5;

    __shared__ float sq[DIM];
    __shared__ int   s_idx[SCAP];
    __shared__ float s_val[SCAP];
    __shared__ float sv[1024];
    __shared__ int   si[1024];
    __shared__ float wv[16];
    __shared__ int   wp[16];
    __shared__ int   wsrc[16];
    __shared__ float s_topv[MAXK];
    __shared__ int   s_topi[MAXK];
    __shared__ float ws[MAXK];
    __shared__ int   s_cnt;
    __shared__ int   s_bin, s_above;
    __shared__ unsigned s_thr;
    __shared__ float s_inv_sh;

    // load query row fp32 into smem (blockDim == DIM)
    sq[tid] = g_query[row * DIM + tid];

    // ---- phase 1: EXACT 64th-largest block max (mapped u16), minus 16-ulp margin ----
    // Soundness: the 64 block-max ELEMENTS have bf16 scores >= exact64, so >= thr; and any
    // exact-top-64 element's bf16 score is within ~0.8% of exact64 — covered by 12.5% margin.
    unsigned* h = reinterpret_cast<unsigned*>(s_idx);   // overlay: 2048 coarse bins
    for (int i = tid; i < 2048; i += 512) h[i] = 0u;
    __syncthreads();
    for (int i = tid; i < nblk; i += 512)
        atomicAdd(&h[g_bmax[row * MAXBLK + i] >> 5], 1u);
    __syncthreads();
    if (tid == 0) {
        int cum = 0;
        int b = 2047;
        for (; b >= 0; --b) {
            int nb = cum + (int)h[b];
            if (nb >= MAXK) break;
            cum = nb;
        }
        if (b < 0) b = 0;          // unreachable for N=500k (nblk >= 64)
        s_bin = b;
        s_above = cum;             // count strictly above bin b
    }
    __syncthreads();
    int bsel = s_bin;
    // fine pass: 32 sub-bins of the selected bin
    for (int i = tid; i < 32; i += 512) h[i] = 0u;
    __syncthreads();
    for (int i = tid; i < nblk; i += 512) {
        unsigned v = g_bmax[row * MAXBLK + i];
        if ((int)(v >> 5) == bsel) atomicAdd(&h[v & 31u], 1u);
    }
    __syncthreads();
    if (tid == 0) {
        int cum = s_above;
        int sub = 31;
        for (; sub >= 0; --sub) {
            cum += (int)h[sub];
            if (cum >= MAXK) break;
        }
        if (sub < 0) sub = 0;
        unsigned val = ((unsigned)bsel << 5) | (unsigned)sub;   // exact 64th-largest (mapped)
        s_thr = (val > 16u) ? (val - 16u) : 0u;                 // 16 bf16-ulp margin (~12.5%)
        s_cnt = 0;
    }
    __syncthreads();
    unsigned thr = s_thr;

    // ---- phase 2: scan row scores, collect candidate indices (warp-aggregated) ----
    const unsigned short* S = g_sbf + (size_t)row * N;
    const uint4* S4 = reinterpret_cast<const uint4*>(S);
    int n4 = N >> 3;
    int iters = (n4 + 2047) >> 11;          // 512 threads x 4 uint4 each
    for (int it = 0; it < iters; ++it) {
        int b4 = (it << 11) + (tid << 2);   // first uint4 of this thread's 4
        unsigned m32 = 0u;
#pragma unroll
        for (int j = 0; j < 4; ++j) {
            int i4 = b4 + j;
            if (i4 < n4) {
                uint4 x = S4[i4];
                unsigned mj = 0u;
                mj |= (map16(x.x & 0xFFFFu) >= thr) ? 1u   : 0u;
                mj |= (map16(x.x >> 16)     >= thr) ? 2u   : 0u;
                mj |= (map16(x.y & 0xFFFFu) >= thr) ? 4u   : 0u;
                mj |= (map16(x.y >> 16)     >= thr) ? 8u   : 0u;
                mj |= (map16(x.z & 0xFFFFu) >= thr) ? 16u  : 0u;
                mj |= (map16(x.z >> 16)     >= thr) ? 32u  : 0u;
                mj |= (map16(x.w & 0xFFFFu) >= thr) ? 64u  : 0u;
                mj |= (map16(x.w >> 16)     >= thr) ? 128u : 0u;
                m32 |= mj << (8 * j);
            }
        }
        int mc = __popc(m32);
        int pfx = mc;
#pragma unroll
        for (int o = 1; o < 32; o <<= 1) {
            int v = __shfl_up_sync(FULLMASK, pfx, o);
            if (lane >= o) pfx += v;
        }
        int wtot = __shfl_sync(FULLMASK, pfx, 31);
        int excl = pfx - mc;
        int base = 0;
        if (lane == 0 && wtot) base = atomicAdd(&s_cnt, wtot);
        base = __shfl_sync(FULLMASK, base, 0);
        int p = base + excl;
        int e0 = b4 << 3;                   // this thread's 32 elements are contiguous
        while (m32) {
            int b = __ffs((int)m32) - 1; m32 &= m32 - 1;
            if (p < SCAP) s_idx[p] = e0 + b;
            ++p;
        }
    }
    // scalar tail (N % 8)
    for (int q = (n4 << 3) + tid; q < N; q += 512) {
        if (map16(S[q]) >= thr) {
            int pp = atomicAdd(&s_cnt, 1);
            if (pp < SCAP) s_idx[pp] = q;
        }
    }
    __syncthreads();
    int cnt = s_cnt; if (cnt > SCAP) cnt = SCAP;

    // ---- phase 3: exact fp32 rescore (one warp per candidate) ----
    for (int c = wid; c < cnt; c += 16) {
        int idx = s_idx[c];
        const float* kp = keys + (size_t)idx * DIM;
        float s = 0.f;
#pragma unroll
        for (int j = 0; j < 4; ++j) {
            float4 kv = *reinterpret_cast<const float4*>(kp + lane * 16 + j * 4);
            float4 qv = *reinterpret_cast<const float4*>(&sq[lane * 16 + j * 4]);
            s += kv.x * qv.x + kv.y * qv.y + kv.z * qv.z + kv.w * qv.w;
        }
#pragma unroll
        for (int o = 16; o; o >>= 1) s += __shfl_xor_sync(FULLMASK, s, o);
        if (lane == 0) s_val[c] = s * SCALE_D;
    }
    __syncthreads();

    // ---- phase 4: exact top-64 merge (value desc, index asc tie-break) ----
    float v0 = NEG_BIG, v1 = NEG_BIG;
    int i0 = 0, i1 = 0;
    float thrf = NEG_BIG;
    int iters2 = (cnt + 2047) >> 11;        // 512 threads x 4 per iter
    for (int it = 0; it < iters2; ++it) {
        int f = (it << 11) + (tid << 2);
        float a0 = (f + 0 < cnt) ? s_val[f + 0] : NEG_BIG;
        float a1 = (f + 1 < cnt) ? s_val[f + 1] : NEG_BIG;
        float a2 = (f + 2 < cnt) ? s_val[f + 2] : NEG_BIG;
        float a3 = (f + 3 < cnt) ? s_val[f + 3] : NEG_BIG;
        topk_insert4(a0, a1, a2, a3, f, v0, v1, i0, i1, thrf);
    }
    i0 = (v0 > NEG_BIG) ? s_idx[i0] : 0x7fffffff;
    i1 = (v1 > NEG_BIG) ? s_idx[i1] : 0x7fffffff;

    sv[wid * 64 + lane]      = v0;  si[wid * 64 + lane]      = i0;
    sv[wid * 64 + 32 + lane] = v1;  si[wid * 64 + 32 + lane] = i1;
    __syncthreads();

    for (int j = 0; j < MAXK; ++j) {
        float bv = sv[wid * 64 + lane];      int bi = si[wid * 64 + lane];      int bp = wid * 64 + lane;
        float ov = sv[wid * 64 + 32 + lane]; int oi = si[wid * 64 + 32 + lane]; int op = wid * 64 + 32 + lane;
        if (ov > bv || (ov == bv && oi < bi)) { bv = ov; bi = oi; bp = op; }
#pragma unroll
        for (int o = 16; o; o >>= 1) {
            float xv = __shfl_xor_sync(FULLMASK, bv, o);
            int   xi = __shfl_xor_sync(FULLMASK, bi, o);
            int   xp = __shfl_xor_sync(FULLMASK, bp, o);
            if (xv > bv || (xv == bv && xi < bi)) { bv = xv; bi = xi; bp = xp; }
        }
        if (lane == 0) { wv[wid] = bv; wp[wid] = bi; wsrc[wid] = bp; }
        __syncthreads();
        if (wid == 0) {
            float cv2 = (lane < 16) ? wv[lane] : NEG_BIG;
            int   ci2 = (lane < 16) ? wp[lane] : 0x7fffffff;
            int   cp2 = (lane < 16) ? wsrc[lane] : 0;
#pragma unroll
            for (int o = 8; o; o >>= 1) {
                float xv = __shfl_xor_sync(FULLMASK, cv2, o);
                int   xi = __shfl_xor_sync(FULLMASK, ci2, o);
                int   xp = __shfl_xor_sync(FULLMASK, cp2, o);
                if (xv > cv2 || (xv == cv2 && xi < ci2)) { cv2 = xv; ci2 = xi; cp2 = xp; }
            }
            if (lane == 0) {
                s_topv[j] = cv2;
                s_topi[j] = ci2;
                sv[cp2] = NEG_BIG;
                si[cp2] = 0x7fffffff;
            }
        }
        __syncthreads();
    }

    // ---- phase 5: softmax(top-kd) + gather + weighted sum ----
    int kd = *kdyn;
    kd = kd < 0 ? 0 : (kd > MAXK ? MAXK : kd);
    if (tid < MAXK) {
        float v = s_topv[tid];
        float m = (kd > 0) ? s_topv[0] : -1e9f;
        float mv = (tid < kd) ? v : -1e9f;
        ws[tid] = expf(mv - m);
    }
    __syncthreads();
    if (tid == 0) {
        float s = 0.f;
#pragma unroll
        for (int j = 0; j < MAXK; ++j) s += ws[j];
        s_inv_sh = 1.0f / s;
    }
    __syncthreads();

    float a = 0.f;
#pragma unroll 4
    for (int j = 0; j < MAXK; ++j) {
        float w = ws[j];
        int ij = s_topi[j];
        if (w != 0.f && ij < N) a += w * P[(size_t)ij * DIM + tid];
    }
    out[row * DIM + tid] = a * s_inv_sh;
}

// ---------------- launcher ----------------
extern "C" void kernel_launch(void* const* d_in, const int* in_sizes, int n_in,
                              void* d_out, int out_size) {
    const float* hidden      = (const float*)d_in[0];
    const float* pool_params = (const float*)d_in[1];
    const float* pool_keys   = (const float*)d_in[2];
    const float* W           = (const float*)d_in[3];
    const float* bias        = (const float*)d_in[4];
    const int*   k_dynamic   = (const int*)d_in[5];
    float* out = (float*)d_out;

    int N = in_sizes[2] / DIM;

    static const size_t SMEMTC = (size_t)(BATCH * QS + TCN * KS) * sizeof(__nv_bfloat16);
    cudaFuncSetAttribute(k_scores_tc, cudaFuncAttributeMaxDynamicSharedMemorySize, (int)SMEMTC);

    int nblk = (N + TCN - 1) / TCN;
    if (nblk > MAXBLK) nblk = MAXBLK;

    k_pool_partial<<<BATCH * 8, 256>>>(hidden);                          // 0
    k_query<<<BATCH, DIM>>>(W, bias);                                    // 1
    k_scores_tc<<<nblk, 256, SMEMTC>>>(pool_keys, N);                    // 2
    k_select<<<BATCH, 512>>>(pool_keys, pool_params, k_dynamic, out, N, nblk); // 3  <-- profile slot
}